// round 2
// baseline (speedup 1.0000x reference)
#include <cuda_runtime.h>
#include <cuda_bf16.h>
#include <math.h>

// Problem constants
#define NB 16        // batch (sentences)
#define LSEQ 128     // seq len
#define DD 768       // hidden
#define MSP 8        // spans per sentence
#define HH 8         // heads
#define JR 30        // span width
#define RR 49        // image regions
#define IMGD 2048
#define NM 128       // N*M spans
#define NQ 3840      // NM*JR rows
#define SR 784       // NB*RR rows

// ---------------- scratch (device globals; no allocs allowed) ----------------
__device__ float g_res  [SR * DD];          // [784,768]
__device__ float g_kproj[SR * HH * DD];     // [784,6144]
__device__ float g_vproj[SR * HH * DD];     // [784,6144]
__device__ float g_ktil [HH * SR * DD];     // [8,784,768]
__device__ float g_vtil [HH * SR * DD];     // [8,784,768]
__device__ float g_span [NQ * DD];          // [3840,768]
__device__ float g_P    [NM * HH * JR * RR];// [128,8,30,49]
__device__ float g_ctx  [NQ * DD];
__device__ float g_att  [NQ * DD];
__device__ float g_cat  [NQ * 2 * DD];      // [3840,1536]
__device__ float g_h1   [NQ * 2 * DD];      // [3840,1536]
__device__ float g_f2   [NQ * DD];          // [3840,768]
__device__ float g_pool [NM * DD];          // [128,768]
__device__ float g_t    [NM * DD];          // [128,768]

// ---------------- generic tiled SGEMM: C = act(A*B + bias) -------------------
// 128x128 tile, BK=8, 256 threads, 8x8 per thread. N must be multiple of 128,
// K multiple of 8. M bounds-checked. TRANSB: B element (k,n) = B[n*ldb + k].
template<int ACT, bool TRANSB>
__global__ __launch_bounds__(256, 2)
void sgemm(const float* __restrict__ A, const float* __restrict__ B,
           const float* __restrict__ bias, float* __restrict__ C,
           int M, int N, int K, int lda, int ldb, int ldc,
           long long aBS, long long bBS, long long cBS)
{
    A += (long long)blockIdx.z * aBS;
    B += (long long)blockIdx.z * bBS;
    C += (long long)blockIdx.z * cBS;

    __shared__ float As[8][128];
    __shared__ float Bs[8][128];

    int tid = threadIdx.x;
    int bm = blockIdx.y * 128, bn = blockIdx.x * 128;
    int tx = tid & 15, ty = tid >> 4;

    float acc[8][8];
    #pragma unroll
    for (int i = 0; i < 8; i++)
        #pragma unroll
        for (int j = 0; j < 8; j++) acc[i][j] = 0.f;

    int arow = tid >> 1, ak4 = (tid & 1) << 2;
    int brow = tid >> 5, bc4 = (tid & 31) << 2;
    int btn  = tid >> 1, btk4 = (tid & 1) << 2;

    for (int k0 = 0; k0 < K; k0 += 8) {
        // A tile 128x8 -> As[k][m]
        float4 av = make_float4(0.f, 0.f, 0.f, 0.f);
        int am = bm + arow;
        if (am < M) av = *(const float4*)(A + (long long)am * lda + k0 + ak4);
        As[ak4    ][arow] = av.x;
        As[ak4 + 1][arow] = av.y;
        As[ak4 + 2][arow] = av.z;
        As[ak4 + 3][arow] = av.w;
        // B tile 8x128 -> Bs[k][n]
        if (!TRANSB) {
            float4 bv = *(const float4*)(B + (long long)(k0 + brow) * ldb + bn + bc4);
            *(float4*)&Bs[brow][bc4] = bv;
        } else {
            float4 bv = *(const float4*)(B + (long long)(bn + btn) * ldb + k0 + btk4);
            Bs[btk4    ][btn] = bv.x;
            Bs[btk4 + 1][btn] = bv.y;
            Bs[btk4 + 2][btn] = bv.z;
            Bs[btk4 + 3][btn] = bv.w;
        }
        __syncthreads();

        #pragma unroll
        for (int kk = 0; kk < 8; kk++) {
            float a[8], b[8];
            *(float4*)(a)     = *(const float4*)&As[kk][ty * 8];
            *(float4*)(a + 4) = *(const float4*)&As[kk][ty * 8 + 4];
            *(float4*)(b)     = *(const float4*)&Bs[kk][tx * 8];
            *(float4*)(b + 4) = *(const float4*)&Bs[kk][tx * 8 + 4];
            #pragma unroll
            for (int i = 0; i < 8; i++)
                #pragma unroll
                for (int j = 0; j < 8; j++)
                    acc[i][j] += a[i] * b[j];
        }
        __syncthreads();
    }

    #pragma unroll
    for (int i = 0; i < 8; i++) {
        int m = bm + ty * 8 + i;
        if (m >= M) continue;
        #pragma unroll
        for (int j = 0; j < 8; j += 4) {
            int n = bn + tx * 8 + j;
            float4 v;
            v.x = acc[i][j];     v.y = acc[i][j + 1];
            v.z = acc[i][j + 2]; v.w = acc[i][j + 3];
            if (bias) {
                v.x += bias[n];     v.y += bias[n + 1];
                v.z += bias[n + 2]; v.w += bias[n + 3];
            }
            if (ACT == 1) {
                v.x = tanhf(v.x); v.y = tanhf(v.y);
                v.z = tanhf(v.z); v.w = tanhf(v.w);
            }
            *(float4*)(C + (long long)m * ldc + n) = v;
        }
    }
}

// ---------------- span gather --------------------------------------------
__global__ void gather_kernel(const float* __restrict__ seq,
                              const int* __restrict__ starts,
                              float* __restrict__ out)
{
    int sq = blockIdx.x;              // 0..3839
    int s = sq / JR, q = sq - s * JR;
    int gstart = starts[s] + (s >> 3) * LSEQ;   // word offset = sentence*128
    int idx = min(gstart + q, NB * LSEQ - 1);
    const float4* src = (const float4*)(seq + (long long)idx * DD);
    float4* dst = (float4*)(out + (long long)sq * DD);
    for (int i = threadIdx.x; i < DD / 4; i += blockDim.x) dst[i] = src[i];
}

// ---------------- attention logits + softmax ------------------------------
// block = (head, span). logits[q,r] = span[q,:]·ktil_h[r,:] / sqrt(768); softmax over r.
__global__ __launch_bounds__(256)
void attn_kernel(const float* __restrict__ span, const float* __restrict__ ktil,
                 float* __restrict__ P)
{
    int h = blockIdx.x;
    int s = blockIdx.y;
    int ns = s >> 3;
    __shared__ float sa[JR][33];
    __shared__ float sb[RR][33];
    __shared__ float sl[JR * RR];

    int tid = threadIdx.x;
    float acc[6] = {0.f, 0.f, 0.f, 0.f, 0.f, 0.f};
    int qi[6], ri[6];
    #pragma unroll
    for (int i = 0; i < 6; i++) {
        int p = tid + 256 * i;
        qi[i] = p / RR;
        ri[i] = p - qi[i] * RR;
    }

    const float* sp = span + (long long)s * JR * DD;
    const float* kp = ktil + (long long)(h * SR + ns * RR) * DD;

    for (int k0 = 0; k0 < DD; k0 += 32) {
        if (tid < 240) {
            int row = tid >> 3, c4 = (tid & 7) << 2;
            float4 v = *(const float4*)(sp + (long long)row * DD + k0 + c4);
            sa[row][c4] = v.x; sa[row][c4 + 1] = v.y;
            sa[row][c4 + 2] = v.z; sa[row][c4 + 3] = v.w;
        }
        for (int i = tid; i < RR * 8; i += 256) {
            int row = i >> 3, c4 = (i & 7) << 2;
            float4 v = *(const float4*)(kp + (long long)row * DD + k0 + c4);
            sb[row][c4] = v.x; sb[row][c4 + 1] = v.y;
            sb[row][c4 + 2] = v.z; sb[row][c4 + 3] = v.w;
        }
        __syncthreads();
        #pragma unroll
        for (int i = 0; i < 6; i++) {
            if (tid + 256 * i < JR * RR) {
                float a = 0.f;
                #pragma unroll
                for (int kk = 0; kk < 32; kk++)
                    a += sa[qi[i]][kk] * sb[ri[i]][kk];
                acc[i] += a;
            }
        }
        __syncthreads();
    }

    const float scale = rsqrtf((float)DD);
    #pragma unroll
    for (int i = 0; i < 6; i++) {
        int p = tid + 256 * i;
        if (p < JR * RR) sl[p] = acc[i] * scale;
    }
    __syncthreads();

    int warp = tid >> 5, lane = tid & 31;
    for (int q = warp; q < JR; q += 8) {
        float v0 = sl[q * RR + lane];
        float v1 = (lane + 32 < RR) ? sl[q * RR + lane + 32] : -3.0e38f;
        float m = fmaxf(v0, v1);
        #pragma unroll
        for (int o = 16; o; o >>= 1) m = fmaxf(m, __shfl_xor_sync(0xffffffffu, m, o));
        float e0 = expf(v0 - m);
        float e1 = (lane + 32 < RR) ? expf(v1 - m) : 0.f;
        float sum = e0 + e1;
        #pragma unroll
        for (int o = 16; o; o >>= 1) sum += __shfl_xor_sync(0xffffffffu, sum, o);
        float inv = 1.f / sum;
        float* Pr = P + (long long)((s * HH + h) * JR + q) * RR;
        Pr[lane] = e0 * inv;
        if (lane + 32 < RR) Pr[lane + 32] = e1 * inv;
    }
}

// ---------------- attention-value + residual ------------------------------
// block = (o-tile, span). ctx[q,o] = sum_h sum_r P[h,q,r]*vtil_h[r,o] + span[q,o]
__global__ __launch_bounds__(256)
void av_kernel(const float* __restrict__ P, const float* __restrict__ vtil,
               const float* __restrict__ span, float* __restrict__ ctx)
{
    int s = blockIdx.y;
    int o = blockIdx.x * 256 + threadIdx.x;
    int ns = s >> 3;
    __shared__ float Ps[HH * JR * RR];   // 11760 floats
    for (int i = threadIdx.x; i < HH * JR * RR; i += 256)
        Ps[i] = P[(long long)s * HH * JR * RR + i];
    __syncthreads();

    float acc[JR];
    #pragma unroll
    for (int q = 0; q < JR; q++) acc[q] = 0.f;

    for (int h = 0; h < HH; h++) {
        const float* vp = vtil + (long long)(h * SR + ns * RR) * DD + o;
        const float* pp = Ps + h * JR * RR;
        for (int r = 0; r < RR; r++) {
            float v = vp[(long long)r * DD];
            #pragma unroll
            for (int q = 0; q < JR; q++)
                acc[q] += pp[q * RR + r] * v;
        }
    }
    const float* sp = span + (long long)s * JR * DD + o;
    float* cp = ctx + (long long)s * JR * DD + o;
    #pragma unroll
    for (int q = 0; q < JR; q++)
        cp[(long long)q * DD] = acc[q] + sp[(long long)q * DD];
}

// ---------------- layernorm -------------------------------------------------
__global__ __launch_bounds__(256)
void ln_kernel(const float* __restrict__ X, const float* __restrict__ g,
               const float* __restrict__ b, float* __restrict__ Y)
{
    int r = blockIdx.x;
    int t = threadIdx.x;
    const float* x = X + (long long)r * DD;
    float v0 = x[t], v1 = x[t + 256], v2 = x[t + 512];
    __shared__ float red[8];

    float s = v0 + v1 + v2;
    #pragma unroll
    for (int o = 16; o; o >>= 1) s += __shfl_xor_sync(0xffffffffu, s, o);
    if ((t & 31) == 0) red[t >> 5] = s;
    __syncthreads();
    if (t == 0) { float z = 0.f; for (int i = 0; i < 8; i++) z += red[i]; red[0] = z; }
    __syncthreads();
    float mu = red[0] * (1.0f / DD);
    __syncthreads();

    float d0 = v0 - mu, d1 = v1 - mu, d2 = v2 - mu;
    float ss = d0 * d0 + d1 * d1 + d2 * d2;
    #pragma unroll
    for (int o = 16; o; o >>= 1) ss += __shfl_xor_sync(0xffffffffu, ss, o);
    if ((t & 31) == 0) red[t >> 5] = ss;
    __syncthreads();
    if (t == 0) { float z = 0.f; for (int i = 0; i < 8; i++) z += red[i]; red[0] = z; }
    __syncthreads();
    float inv = rsqrtf(red[0] * (1.0f / DD) + 1e-5f);

    float* y = Y + (long long)r * DD;
    y[t]       = d0 * inv * g[t]       + b[t];
    y[t + 256] = d1 * inv * g[t + 256] + b[t + 256];
    y[t + 512] = d2 * inv * g[t + 512] + b[t + 512];
}

// ---------------- concat [span | att] ---------------------------------------
__global__ void concat_kernel(const float* __restrict__ a, const float* __restrict__ bsrc,
                              float* __restrict__ out)
{
    long long i = (long long)blockIdx.x * blockDim.x + threadIdx.x; // float4 index
    if (i >= (long long)NQ * 384) return;
    int r = (int)(i / 384), c = (int)(i - (long long)r * 384);
    float4 v;
    if (c < 192) v = ((const float4*)a)[(long long)r * 192 + c];
    else         v = ((const float4*)bsrc)[(long long)r * 192 + c - 192];
    ((float4*)out)[i] = v;
}

// ---------------- unary score + masked softmax + pooling --------------------
__global__ __launch_bounds__(256)
void pool_kernel(const float* __restrict__ F2, const float* __restrict__ W_un,
                 const float* __restrict__ b_un, const int* __restrict__ starts,
                 const int* __restrict__ ends, float* __restrict__ pooled)
{
    int s = blockIdx.x;
    __shared__ float sc[JR];
    __shared__ float pr[32];
    int tid = threadIdx.x, warp = tid >> 5, lane = tid & 31;

    for (int q = warp; q < JR; q += 8) {
        const float* row = F2 + (long long)(s * JR + q) * DD;
        float acc = 0.f;
        for (int k = lane; k < DD; k += 32) acc += row[k] * W_un[k];
        #pragma unroll
        for (int o = 16; o; o >>= 1) acc += __shfl_xor_sync(0xffffffffu, acc, o);
        if (lane == 0) sc[q] = acc + b_un[0];
    }
    __syncthreads();

    if (tid < 32) {
        int width = ends[s] - starts[s] + 1;
        float v = -3.0e38f;
        if (tid < JR) {
            v = sc[tid];
            if (tid >= width) v += -10000.0f;
        }
        float m = v;
        #pragma unroll
        for (int o = 16; o; o >>= 1) m = fmaxf(m, __shfl_xor_sync(0xffffffffu, m, o));
        float e = (tid < JR) ? expf(v - m) : 0.f;
        float sum = e;
        #pragma unroll
        for (int o = 16; o; o >>= 1) sum += __shfl_xor_sync(0xffffffffu, sum, o);
        pr[tid] = (tid < JR) ? e / sum : 0.f;
    }
    __syncthreads();

    for (int o = tid; o < DD; o += 256) {
        float acc = 0.f;
        #pragma unroll
        for (int q = 0; q < JR; q++)
            acc += pr[q] * F2[(long long)(s * JR + q) * DD + o];
        pooled[(long long)s * DD + o] = acc;
    }
}

// ---------------- classifier ------------------------------------------------
__global__ void cls_kernel(const float* __restrict__ T, const float* __restrict__ Wc,
                           const float* __restrict__ bc, float* __restrict__ out)
{
    int s = blockIdx.x;
    int c = threadIdx.x >> 5, lane = threadIdx.x & 31;
    const float* t = T + (long long)s * DD;
    float acc = 0.f;
    for (int k = lane; k < DD; k += 32) acc += t[k] * Wc[k * 4 + c];
    #pragma unroll
    for (int o = 16; o; o >>= 1) acc += __shfl_xor_sync(0xffffffffu, acc, o);
    if (lane == 0) out[s * 4 + c] = acc + bc[c];
}

// ---------------- launcher --------------------------------------------------
extern "C" void kernel_launch(void* const* d_in, const int* in_sizes, int n_in,
                              void* d_out, int out_size)
{
    const float* enc_img  = (const float*)d_in[0];
    const float* seq      = (const float*)d_in[1];
    const int*   starts   = (const int*)d_in[3];
    const int*   ends     = (const int*)d_in[4];
    const float* W_align  = (const float*)d_in[5];
    const float* b_align  = (const float*)d_in[6];
    const float* Wq       = (const float*)d_in[7];
    const float* Wk       = (const float*)d_in[8];
    const float* Wv       = (const float*)d_in[9];
    const float* Wfc      = (const float*)d_in[10];
    const float* ln_g     = (const float*)d_in[11];
    const float* ln_b     = (const float*)d_in[12];
    const float* W_a1     = (const float*)d_in[13];
    const float* b_a1     = (const float*)d_in[14];
    const float* W_a2     = (const float*)d_in[15];
    const float* b_a2     = (const float*)d_in[16];
    const float* W_un     = (const float*)d_in[17];
    const float* b_un     = (const float*)d_in[18];
    const float* W_dense  = (const float*)d_in[19];
    const float* b_dense  = (const float*)d_in[20];
    const float* W_cls    = (const float*)d_in[21];
    const float* b_cls    = (const float*)d_in[22];
    float* out = (float*)d_out;

    float *res, *kproj, *vproj, *ktil, *vtil, *span, *P, *ctx, *att, *cat, *h1, *f2, *pool, *tb;
    cudaGetSymbolAddress((void**)&res,   g_res);
    cudaGetSymbolAddress((void**)&kproj, g_kproj);
    cudaGetSymbolAddress((void**)&vproj, g_vproj);
    cudaGetSymbolAddress((void**)&ktil,  g_ktil);
    cudaGetSymbolAddress((void**)&vtil,  g_vtil);
    cudaGetSymbolAddress((void**)&span,  g_span);
    cudaGetSymbolAddress((void**)&P,     g_P);
    cudaGetSymbolAddress((void**)&ctx,   g_ctx);
    cudaGetSymbolAddress((void**)&att,   g_att);
    cudaGetSymbolAddress((void**)&cat,   g_cat);
    cudaGetSymbolAddress((void**)&h1,    g_h1);
    cudaGetSymbolAddress((void**)&f2,    g_f2);
    cudaGetSymbolAddress((void**)&pool,  g_pool);
    cudaGetSymbolAddress((void**)&tb,    g_t);

    // 0) res = enc_img @ W_align + b_align       [784,768]
    sgemm<0, false><<<dim3(768 / 128, (SR + 127) / 128, 1), 256>>>(
        enc_img, W_align, b_align, res, SR, 768, 2048, 2048, 768, 768, 0, 0, 0);
    // 1) kproj = res @ Wk                         [784,6144]
    sgemm<0, false><<<dim3(6144 / 128, (SR + 127) / 128, 1), 256>>>(
        res, Wk, nullptr, kproj, SR, 6144, 768, 768, 6144, 6144, 0, 0, 0);
    // 2) vproj = res @ Wv                         [784,6144]
    sgemm<0, false><<<dim3(6144 / 128, (SR + 127) / 128, 1), 256>>>(
        res, Wv, nullptr, vproj, SR, 6144, 768, 768, 6144, 6144, 0, 0, 0);
    // 3) ktil_h = kproj_h @ Wq_h^T (batched over heads)  [8,784,768]
    sgemm<0, true><<<dim3(768 / 128, (SR + 127) / 128, HH), 256>>>(
        kproj, Wq, nullptr, ktil, SR, 768, 768, 6144, 6144, 768,
        768LL, 768LL, (long long)SR * 768);
    // 4) vtil_h = vproj_h @ Wfc_h (batched over heads)   [8,784,768]
    sgemm<0, false><<<dim3(768 / 128, (SR + 127) / 128, HH), 256>>>(
        vproj, Wfc, nullptr, vtil, SR, 768, 768, 6144, 768, 768,
        768LL, 768LL * 768LL, (long long)SR * 768);
    // 5) span gather
    gather_kernel<<<NQ, 192>>>(seq, starts, span);
    // 6) attention logits + softmax -> P
    attn_kernel<<<dim3(HH, NM), 256>>>(span, ktil, P);
    // 7) AV + residual -> ctx
    av_kernel<<<dim3(3, NM), 256>>>(P, vtil, span, ctx);
    // 8) layernorm -> att
    ln_kernel<<<NQ, 256>>>(ctx, ln_g, ln_b, att);
    // 9) concat [span | att] -> cat [3840,1536]
    concat_kernel<<<(int)(((long long)NQ * 384 + 255) / 256), 256>>>(span, att, cat);
    // 10) h1 = tanh(cat @ W_a1 + b_a1)            [3840,1536]
    sgemm<1, false><<<dim3(1536 / 128, NQ / 128, 1), 256>>>(
        cat, W_a1, b_a1, h1, NQ, 1536, 1536, 1536, 1536, 1536, 0, 0, 0);
    // 11) f2 = h1 @ W_a2 + b_a2                   [3840,768]
    sgemm<0, false><<<dim3(768 / 128, NQ / 128, 1), 256>>>(
        h1, W_a2, b_a2, f2, NQ, 768, 1536, 1536, 768, 768, 0, 0, 0);
    // 12) score + masked softmax + pooled         [128,768]
    pool_kernel<<<NM, 256>>>(f2, W_un, b_un, starts, ends, pool);
    // 13) t = tanh(pool @ W_dense + b_dense)      [128,768]
    sgemm<1, false><<<dim3(768 / 128, 1, 1), 256>>>(
        pool, W_dense, b_dense, tb, NM, 768, 768, 768, 768, 768, 0, 0, 0);
    // 14) logits = t @ W_cls + b_cls              [128,4]
    cls_kernel<<<NM, 128>>>(tb, W_cls, b_cls, out);
}

// round 3
// speedup vs baseline: 1.8614x; 1.8614x over previous
#include <cuda_runtime.h>
#include <cuda_bf16.h>
#include <math.h>
#include <stdint.h>

// Problem constants
#define NB 16
#define LSEQ 128
#define DD 768
#define MSP 8
#define HH 8
#define JR 30
#define RR 49
#define NM 128       // N*M spans
#define NQ 3840      // NM*JR rows
#define SR 784       // NB*RR rows

// ---------------- scratch ----------------
__device__ float g_res  [SR * DD];
__device__ float g_kproj[SR * HH * DD];
__device__ float g_vproj[SR * HH * DD];
__device__ float g_ktil [HH * SR * DD];
__device__ float g_vtil [HH * SR * DD];
__device__ float g_span [NQ * DD];
__device__ float g_P    [NM * HH * JR * RR];
__device__ float g_ctx  [NQ * DD];
__device__ float g_cat  [NQ * 2 * DD];
__device__ float g_h1   [NQ * 2 * DD];
__device__ float g_f2   [NQ * DD];
__device__ float g_pool [NM * DD];
__device__ float g_t    [NM * DD];

// ---------------- tf32 helpers ----------------
__device__ __forceinline__ uint32_t f2tf(float x) {
    uint32_t u;
    asm("cvt.rna.tf32.f32 %0, %1;" : "=r"(u) : "f"(x));
    return u;
}

__device__ __forceinline__ void mma8(float* c, const uint32_t* a, const uint32_t* b) {
    asm volatile(
        "mma.sync.aligned.m16n8k8.row.col.f32.tf32.tf32.f32 "
        "{%0,%1,%2,%3},{%4,%5,%6,%7},{%8,%9},{%0,%1,%2,%3};"
        : "+f"(c[0]), "+f"(c[1]), "+f"(c[2]), "+f"(c[3])
        : "r"(a[0]), "r"(a[1]), "r"(a[2]), "r"(a[3]), "r"(b[0]), "r"(b[1]));
}

// ---------------- TF32 tensor-core GEMM: C = act(A*B + bias) ----------------
// Block tile 128x128, BK=16, double-buffered smem, 256 threads (8 warps of 64x32).
// N must be multiple of 128, K multiple of 16; M bounds-checked.
// TRANSB: B element (k,n) = B[n*ldb + k].
template<int ACT, bool TRANSB>
__global__ __launch_bounds__(256, 2)
void gemmtf(const float* __restrict__ A, const float* __restrict__ B,
            const float* __restrict__ bias, float* __restrict__ C,
            int M, int N, int K, int lda, int ldb, int ldc,
            long long aBS, long long bBS, long long cBS)
{
    A += (long long)blockIdx.z * aBS;
    B += (long long)blockIdx.z * bBS;
    C += (long long)blockIdx.z * cBS;

    __shared__ uint32_t As[2][16][132];
    __shared__ uint32_t Bs[2][16][132];

    const int tid = threadIdx.x;
    const int warp = tid >> 5, lane = tid & 31;
    const int g = lane >> 2, tig = lane & 3;       // groupID, threadInGroup
    const int wm = warp & 1, wn = warp >> 1;       // 2 x 4 warp grid: 64 x 32 per warp
    const int bm = blockIdx.y * 128, bn = blockIdx.x * 128;

    float acc[4][4][4];
    #pragma unroll
    for (int mt = 0; mt < 4; mt++)
        #pragma unroll
        for (int nt = 0; nt < 4; nt++)
            #pragma unroll
            for (int i = 0; i < 4; i++) acc[mt][nt][i] = 0.f;

    // loader index precompute
    // A: float4 idx i: m = i&127, kq = i>>7 (k = 4*kq); 512 f4/tile, 2 per thread
    const int a_m  = tid & 127;
    const int a_kq0 = tid >> 7;                  // 0..1 ; second is +2
    // B (no trans): i: n4 = i&31, kr = i>>5; 2 per thread
    const int b_n4 = tid & 31;
    const int b_kr0 = tid >> 5;                  // 0..7 ; second is +8
    // B (trans): i: n = i&127, kq = i>>7
    const int bt_n = tid & 127;
    const int bt_kq0 = tid >> 7;

    float4 ra[2], rb[2];

    // ---- load tile 0 ----
    {
        #pragma unroll
        for (int j = 0; j < 2; j++) {
            int m = bm + a_m, kq = a_kq0 + 2 * j;
            ra[j] = (m < M) ? *(const float4*)(A + (long long)m * lda + 4 * kq)
                            : make_float4(0.f, 0.f, 0.f, 0.f);
        }
        #pragma unroll
        for (int j = 0; j < 2; j++) {
            if (!TRANSB) {
                int kr = b_kr0 + 8 * j;
                rb[j] = *(const float4*)(B + (long long)kr * ldb + bn + 4 * b_n4);
            } else {
                int kq = bt_kq0 + 2 * j;
                rb[j] = *(const float4*)(B + (long long)(bn + bt_n) * ldb + 4 * kq);
            }
        }
        #pragma unroll
        for (int j = 0; j < 2; j++) {
            int kq = a_kq0 + 2 * j;
            As[0][4 * kq + 0][a_m] = f2tf(ra[j].x);
            As[0][4 * kq + 1][a_m] = f2tf(ra[j].y);
            As[0][4 * kq + 2][a_m] = f2tf(ra[j].z);
            As[0][4 * kq + 3][a_m] = f2tf(ra[j].w);
            if (!TRANSB) {
                int kr = b_kr0 + 8 * j;
                uint4 u;
                u.x = f2tf(rb[j].x); u.y = f2tf(rb[j].y);
                u.z = f2tf(rb[j].z); u.w = f2tf(rb[j].w);
                *(uint4*)&Bs[0][kr][4 * b_n4] = u;
            } else {
                int kq = bt_kq0 + 2 * j;
                Bs[0][4 * kq + 0][bt_n] = f2tf(rb[j].x);
                Bs[0][4 * kq + 1][bt_n] = f2tf(rb[j].y);
                Bs[0][4 * kq + 2][bt_n] = f2tf(rb[j].z);
                Bs[0][4 * kq + 3][bt_n] = f2tf(rb[j].w);
            }
        }
    }
    __syncthreads();

    for (int k0 = 0; k0 < K; k0 += 16) {
        const int buf = (k0 >> 4) & 1;
        const bool more = (k0 + 16) < K;

        // prefetch next tile into registers
        if (more) {
            #pragma unroll
            for (int j = 0; j < 2; j++) {
                int m = bm + a_m, kq = a_kq0 + 2 * j;
                ra[j] = (m < M) ? *(const float4*)(A + (long long)m * lda + k0 + 16 + 4 * kq)
                                : make_float4(0.f, 0.f, 0.f, 0.f);
            }
            #pragma unroll
            for (int j = 0; j < 2; j++) {
                if (!TRANSB) {
                    int kr = b_kr0 + 8 * j;
                    rb[j] = *(const float4*)(B + (long long)(k0 + 16 + kr) * ldb + bn + 4 * b_n4);
                } else {
                    int kq = bt_kq0 + 2 * j;
                    rb[j] = *(const float4*)(B + (long long)(bn + bt_n) * ldb + k0 + 16 + 4 * kq);
                }
            }
        }

        // compute on buf
        #pragma unroll
        for (int kk = 0; kk < 2; kk++) {
            const int kb = kk * 8;
            uint32_t af[4][4], bf[4][2];
            #pragma unroll
            for (int mt = 0; mt < 4; mt++) {
                int r = wm * 64 + mt * 16 + g;
                af[mt][0] = As[buf][kb + tig][r];
                af[mt][1] = As[buf][kb + tig][r + 8];
                af[mt][2] = As[buf][kb + tig + 4][r];
                af[mt][3] = As[buf][kb + tig + 4][r + 8];
            }
            #pragma unroll
            for (int nt = 0; nt < 4; nt++) {
                int c = wn * 32 + nt * 8 + g;
                bf[nt][0] = Bs[buf][kb + tig][c];
                bf[nt][1] = Bs[buf][kb + tig + 4][c];
            }
            #pragma unroll
            for (int mt = 0; mt < 4; mt++)
                #pragma unroll
                for (int nt = 0; nt < 4; nt++)
                    mma8(acc[mt][nt], af[mt], bf[nt]);
        }

        // store prefetched into other buffer
        if (more) {
            const int nb = buf ^ 1;
            #pragma unroll
            for (int j = 0; j < 2; j++) {
                int kq = a_kq0 + 2 * j;
                As[nb][4 * kq + 0][a_m] = f2tf(ra[j].x);
                As[nb][4 * kq + 1][a_m] = f2tf(ra[j].y);
                As[nb][4 * kq + 2][a_m] = f2tf(ra[j].z);
                As[nb][4 * kq + 3][a_m] = f2tf(ra[j].w);
                if (!TRANSB) {
                    int kr = b_kr0 + 8 * j;
                    uint4 u;
                    u.x = f2tf(rb[j].x); u.y = f2tf(rb[j].y);
                    u.z = f2tf(rb[j].z); u.w = f2tf(rb[j].w);
                    *(uint4*)&Bs[nb][kr][4 * b_n4] = u;
                } else {
                    int kq2 = bt_kq0 + 2 * j;
                    Bs[nb][4 * kq2 + 0][bt_n] = f2tf(rb[j].x);
                    Bs[nb][4 * kq2 + 1][bt_n] = f2tf(rb[j].y);
                    Bs[nb][4 * kq2 + 2][bt_n] = f2tf(rb[j].z);
                    Bs[nb][4 * kq2 + 3][bt_n] = f2tf(rb[j].w);
                }
            }
        }
        __syncthreads();
    }

    // epilogue
    #pragma unroll
    for (int mt = 0; mt < 4; mt++) {
        int r0 = bm + wm * 64 + mt * 16 + g;
        int r1 = r0 + 8;
        #pragma unroll
        for (int nt = 0; nt < 4; nt++) {
            int c = bn + wn * 32 + nt * 8 + 2 * tig;
            float b0 = bias ? bias[c] : 0.f;
            float b1 = bias ? bias[c + 1] : 0.f;
            float v0 = acc[mt][nt][0] + b0, v1 = acc[mt][nt][1] + b1;
            float v2 = acc[mt][nt][2] + b0, v3 = acc[mt][nt][3] + b1;
            if (ACT == 1) { v0 = tanhf(v0); v1 = tanhf(v1); v2 = tanhf(v2); v3 = tanhf(v3); }
            if (r0 < M) *(float2*)(C + (long long)r0 * ldc + c) = make_float2(v0, v1);
            if (r1 < M) *(float2*)(C + (long long)r1 * ldc + c) = make_float2(v2, v3);
        }
    }
}

// ---------------- span gather (also fills cat left half) -----------------
__global__ void gather_kernel(const float* __restrict__ seq,
                              const int* __restrict__ starts,
                              float* __restrict__ out, float* __restrict__ cat)
{
    int sq = blockIdx.x;
    int s = sq / JR, q = sq - s * JR;
    int gstart = starts[s] + (s >> 3) * LSEQ;
    int idx = min(gstart + q, NB * LSEQ - 1);
    const float4* src = (const float4*)(seq + (long long)idx * DD);
    float4* dst = (float4*)(out + (long long)sq * DD);
    float4* dst2 = (float4*)(cat + (long long)sq * 2 * DD);
    for (int i = threadIdx.x; i < DD / 4; i += blockDim.x) {
        float4 v = src[i];
        dst[i] = v;
        dst2[i] = v;
    }
}

// ---------------- attention logits + softmax ------------------------------
__global__ __launch_bounds__(256)
void attn_kernel(const float* __restrict__ span, const float* __restrict__ ktil,
                 float* __restrict__ P)
{
    int h = blockIdx.x;
    int s = blockIdx.y;
    int ns = s >> 3;
    __shared__ float sa[JR][33];
    __shared__ float sb[RR][33];
    __shared__ float sl[JR * RR];

    int tid = threadIdx.x;
    float acc[6] = {0.f, 0.f, 0.f, 0.f, 0.f, 0.f};
    int qi[6], ri[6];
    #pragma unroll
    for (int i = 0; i < 6; i++) {
        int p = tid + 256 * i;
        qi[i] = p / RR;
        ri[i] = p - qi[i] * RR;
    }

    const float* sp = span + (long long)s * JR * DD;
    const float* kp = ktil + (long long)(h * SR + ns * RR) * DD;

    for (int k0 = 0; k0 < DD; k0 += 32) {
        if (tid < 240) {
            int row = tid >> 3, c4 = (tid & 7) << 2;
            float4 v = *(const float4*)(sp + (long long)row * DD + k0 + c4);
            sa[row][c4] = v.x; sa[row][c4 + 1] = v.y;
            sa[row][c4 + 2] = v.z; sa[row][c4 + 3] = v.w;
        }
        for (int i = tid; i < RR * 8; i += 256) {
            int row = i >> 3, c4 = (i & 7) << 2;
            float4 v = *(const float4*)(kp + (long long)row * DD + k0 + c4);
            sb[row][c4] = v.x; sb[row][c4 + 1] = v.y;
            sb[row][c4 + 2] = v.z; sb[row][c4 + 3] = v.w;
        }
        __syncthreads();
        #pragma unroll
        for (int i = 0; i < 6; i++) {
            if (tid + 256 * i < JR * RR) {
                float a = 0.f;
                #pragma unroll
                for (int kk = 0; kk < 32; kk++)
                    a += sa[qi[i]][kk] * sb[ri[i]][kk];
                acc[i] += a;
            }
        }
        __syncthreads();
    }

    const float scale = rsqrtf((float)DD);
    #pragma unroll
    for (int i = 0; i < 6; i++) {
        int p = tid + 256 * i;
        if (p < JR * RR) sl[p] = acc[i] * scale;
    }
    __syncthreads();

    int warp = tid >> 5, lane = tid & 31;
    for (int q = warp; q < JR; q += 8) {
        float v0 = sl[q * RR + lane];
        float v1 = (lane + 32 < RR) ? sl[q * RR + lane + 32] : -3.0e38f;
        float m = fmaxf(v0, v1);
        #pragma unroll
        for (int o = 16; o; o >>= 1) m = fmaxf(m, __shfl_xor_sync(0xffffffffu, m, o));
        float e0 = expf(v0 - m);
        float e1 = (lane + 32 < RR) ? expf(v1 - m) : 0.f;
        float sum = e0 + e1;
        #pragma unroll
        for (int o = 16; o; o >>= 1) sum += __shfl_xor_sync(0xffffffffu, sum, o);
        float inv = 1.f / sum;
        float* Pr = P + (long long)((s * HH + h) * JR + q) * RR;
        Pr[lane] = e0 * inv;
        if (lane + 32 < RR) Pr[lane + 32] = e1 * inv;
    }
}

// ---------------- attention-value + residual ------------------------------
__global__ __launch_bounds__(256)
void av_kernel(const float* __restrict__ P, const float* __restrict__ vtil,
               const float* __restrict__ span, float* __restrict__ ctx)
{
    int s = blockIdx.y;
    int o = blockIdx.x * 256 + threadIdx.x;
    int ns = s >> 3;
    __shared__ float Ps[HH * JR * RR];
    for (int i = threadIdx.x; i < HH * JR * RR; i += 256)
        Ps[i] = P[(long long)s * HH * JR * RR + i];
    __syncthreads();

    float acc[JR];
    #pragma unroll
    for (int q = 0; q < JR; q++) acc[q] = 0.f;

    for (int h = 0; h < HH; h++) {
        const float* vp = vtil + (long long)(h * SR + ns * RR) * DD + o;
        const float* pp = Ps + h * JR * RR;
        for (int r = 0; r < RR; r++) {
            float v = vp[(long long)r * DD];
            #pragma unroll
            for (int q = 0; q < JR; q++)
                acc[q] += pp[q * RR + r] * v;
        }
    }
    const float* sp = span + (long long)s * JR * DD + o;
    float* cp = ctx + (long long)s * JR * DD + o;
    #pragma unroll
    for (int q = 0; q < JR; q++)
        cp[(long long)q * DD] = acc[q] + sp[(long long)q * DD];
}

// ---------------- layernorm (writes into strided output) -------------------
__global__ __launch_bounds__(256)
void ln_kernel(const float* __restrict__ X, const float* __restrict__ g,
               const float* __restrict__ b, float* __restrict__ Y, int ostride)
{
    int r = blockIdx.x;
    int t = threadIdx.x;
    const float* x = X + (long long)r * DD;
    float v0 = x[t], v1 = x[t + 256], v2 = x[t + 512];
    __shared__ float red[8];

    float s = v0 + v1 + v2;
    #pragma unroll
    for (int o = 16; o; o >>= 1) s += __shfl_xor_sync(0xffffffffu, s, o);
    if ((t & 31) == 0) red[t >> 5] = s;
    __syncthreads();
    if (t == 0) { float z = 0.f; for (int i = 0; i < 8; i++) z += red[i]; red[0] = z; }
    __syncthreads();
    float mu = red[0] * (1.0f / DD);
    __syncthreads();

    float d0 = v0 - mu, d1 = v1 - mu, d2 = v2 - mu;
    float ss = d0 * d0 + d1 * d1 + d2 * d2;
    #pragma unroll
    for (int o = 16; o; o >>= 1) ss += __shfl_xor_sync(0xffffffffu, ss, o);
    if ((t & 31) == 0) red[t >> 5] = ss;
    __syncthreads();
    if (t == 0) { float z = 0.f; for (int i = 0; i < 8; i++) z += red[i]; red[0] = z; }
    __syncthreads();
    float inv = rsqrtf(red[0] * (1.0f / DD) + 1e-5f);

    float* y = Y + (long long)r * ostride;
    y[t]       = d0 * inv * g[t]       + b[t];
    y[t + 256] = d1 * inv * g[t + 256] + b[t + 256];
    y[t + 512] = d2 * inv * g[t + 512] + b[t + 512];
}

// ---------------- unary score + masked softmax + pooling --------------------
__global__ __launch_bounds__(256)
void pool_kernel(const float* __restrict__ F2, const float* __restrict__ W_un,
                 const float* __restrict__ b_un, const int* __restrict__ starts,
                 const int* __restrict__ ends, float* __restrict__ pooled)
{
    int s = blockIdx.x;
    __shared__ float sc[JR];
    __shared__ float pr[32];
    int tid = threadIdx.x, warp = tid >> 5, lane = tid & 31;

    for (int q = warp; q < JR; q += 8) {
        const float* row = F2 + (long long)(s * JR + q) * DD;
        float acc = 0.f;
        for (int k = lane; k < DD; k += 32) acc += row[k] * W_un[k];
        #pragma unroll
        for (int o = 16; o; o >>= 1) acc += __shfl_xor_sync(0xffffffffu, acc, o);
        if (lane == 0) sc[q] = acc + b_un[0];
    }
    __syncthreads();

    if (tid < 32) {
        int width = ends[s] - starts[s] + 1;
        float v = -3.0e38f;
        if (tid < JR) {
            v = sc[tid];
            if (tid >= width) v += -10000.0f;
        }
        float m = v;
        #pragma unroll
        for (int o = 16; o; o >>= 1) m = fmaxf(m, __shfl_xor_sync(0xffffffffu, m, o));
        float e = (tid < JR) ? expf(v - m) : 0.f;
        float sum = e;
        #pragma unroll
        for (int o = 16; o; o >>= 1) sum += __shfl_xor_sync(0xffffffffu, sum, o);
        pr[tid] = (tid < JR) ? e / sum : 0.f;
    }
    __syncthreads();

    for (int o = tid; o < DD; o += 256) {
        float acc = 0.f;
        #pragma unroll
        for (int q = 0; q < JR; q++)
            acc += pr[q] * F2[(long long)(s * JR + q) * DD + o];
        pooled[(long long)s * DD + o] = acc;
    }
}

// ---------------- classifier ------------------------------------------------
__global__ void cls_kernel(const float* __restrict__ T, const float* __restrict__ Wc,
                           const float* __restrict__ bc, float* __restrict__ out)
{
    int s = blockIdx.x;
    int c = threadIdx.x >> 5, lane = threadIdx.x & 31;
    const float* t = T + (long long)s * DD;
    float acc = 0.f;
    for (int k = lane; k < DD; k += 32) acc += t[k] * Wc[k * 4 + c];
    #pragma unroll
    for (int o = 16; o; o >>= 1) acc += __shfl_xor_sync(0xffffffffu, acc, o);
    if (lane == 0) out[s * 4 + c] = acc + bc[c];
}

// ---------------- launcher --------------------------------------------------
extern "C" void kernel_launch(void* const* d_in, const int* in_sizes, int n_in,
                              void* d_out, int out_size)
{
    const float* enc_img  = (const float*)d_in[0];
    const float* seq      = (const float*)d_in[1];
    const int*   starts   = (const int*)d_in[3];
    const int*   ends     = (const int*)d_in[4];
    const float* W_align  = (const float*)d_in[5];
    const float* b_align  = (const float*)d_in[6];
    const float* Wq       = (const float*)d_in[7];
    const float* Wk       = (const float*)d_in[8];
    const float* Wv       = (const float*)d_in[9];
    const float* Wfc      = (const float*)d_in[10];
    const float* ln_g     = (const float*)d_in[11];
    const float* ln_b     = (const float*)d_in[12];
    const float* W_a1     = (const float*)d_in[13];
    const float* b_a1     = (const float*)d_in[14];
    const float* W_a2     = (const float*)d_in[15];
    const float* b_a2     = (const float*)d_in[16];
    const float* W_un     = (const float*)d_in[17];
    const float* b_un     = (const float*)d_in[18];
    const float* W_dense  = (const float*)d_in[19];
    const float* b_dense  = (const float*)d_in[20];
    const float* W_cls    = (const float*)d_in[21];
    const float* b_cls    = (const float*)d_in[22];
    float* out = (float*)d_out;

    float *res, *kproj, *vproj, *ktil, *vtil, *span, *P, *ctx, *cat, *h1, *f2, *pool, *tb;
    cudaGetSymbolAddress((void**)&res,   g_res);
    cudaGetSymbolAddress((void**)&kproj, g_kproj);
    cudaGetSymbolAddress((void**)&vproj, g_vproj);
    cudaGetSymbolAddress((void**)&ktil,  g_ktil);
    cudaGetSymbolAddress((void**)&vtil,  g_vtil);
    cudaGetSymbolAddress((void**)&span,  g_span);
    cudaGetSymbolAddress((void**)&P,     g_P);
    cudaGetSymbolAddress((void**)&ctx,   g_ctx);
    cudaGetSymbolAddress((void**)&cat,   g_cat);
    cudaGetSymbolAddress((void**)&h1,    g_h1);
    cudaGetSymbolAddress((void**)&f2,    g_f2);
    cudaGetSymbolAddress((void**)&pool,  g_pool);
    cudaGetSymbolAddress((void**)&tb,    g_t);

    // 0) res = enc_img @ W_align + b_align       [784,768]
    gemmtf<0, false><<<dim3(6, 7, 1), 256>>>(
        enc_img, W_align, b_align, res, SR, 768, 2048, 2048, 768, 768, 0, 0, 0);
    // 1) kproj = res @ Wk                         [784,6144]
    gemmtf<0, false><<<dim3(48, 7, 1), 256>>>(
        res, Wk, nullptr, kproj, SR, 6144, 768, 768, 6144, 6144, 0, 0, 0);
    // 2) vproj = res @ Wv                         [784,6144]
    gemmtf<0, false><<<dim3(48, 7, 1), 256>>>(
        res, Wv, nullptr, vproj, SR, 6144, 768, 768, 6144, 6144, 0, 0, 0);
    // 3) ktil_h = kproj_h @ Wq_h^T (batched)      [8,784,768]
    gemmtf<0, true><<<dim3(6, 7, HH), 256>>>(
        kproj, Wq, nullptr, ktil, SR, 768, 768, 6144, 6144, 768,
        768LL, 768LL, (long long)SR * 768);
    // 4) vtil_h = vproj_h @ Wfc_h (batched)       [8,784,768]
    gemmtf<0, false><<<dim3(6, 7, HH), 256>>>(
        vproj, Wfc, nullptr, vtil, SR, 768, 768, 6144, 768, 768,
        768LL, 768LL * 768LL, (long long)SR * 768);
    // 5) span gather (also fills cat left half)
    gather_kernel<<<NQ, 192>>>(seq, starts, span, cat);
    // 6) attention logits + softmax -> P
    attn_kernel<<<dim3(HH, NM), 256>>>(span, ktil, P);
    // 7) AV + residual -> ctx
    av_kernel<<<dim3(3, NM), 256>>>(P, vtil, span, ctx);
    // 8) layernorm -> cat right half (stride 1536)
    ln_kernel<<<NQ, 256>>>(ctx, ln_g, ln_b, cat + DD, 2 * DD);
    // 10) h1 = tanh(cat @ W_a1 + b_a1)            [3840,1536]
    gemmtf<1, false><<<dim3(12, 30, 1), 256>>>(
        cat, W_a1, b_a1, h1, NQ, 1536, 1536, 1536, 1536, 1536, 0, 0, 0);
    // 11) f2 = h1 @ W_a2 + b_a2                   [3840,768]
    gemmtf<0, false><<<dim3(6, 30, 1), 256>>>(
        h1, W_a2, b_a2, f2, NQ, 768, 1536, 1536, 768, 768, 0, 0, 0);
    // 12) score + masked softmax + pooled         [128,768]
    pool_kernel<<<NM, 256>>>(f2, W_un, b_un, starts, ends, pool);
    // 13) t = tanh(pool @ W_dense + b_dense)      [128,768]
    gemmtf<1, false><<<dim3(6, 1, 1), 256>>>(
        pool, W_dense, b_dense, tb, NM, 768, 768, 768, 768, 768, 0, 0, 0);
    // 14) logits = t @ W_cls + b_cls              [128,4]
    cls_kernel<<<NM, 128>>>(tb, W_cls, b_cls, out);
}

// round 4
// speedup vs baseline: 2.4178x; 1.2989x over previous
#include <cuda_runtime.h>
#include <cuda_bf16.h>
#include <math.h>
#include <stdint.h>

// Problem constants
#define NB 16
#define LSEQ 128
#define DD 768
#define HH 8
#define JR 30
#define RR 49
#define NM 128       // N*M spans
#define NQ 3840      // NM*JR rows
#define SR 784       // NB*RR rows

// ---------------- scratch ----------------
__device__ __align__(16) float g_res  [SR * DD];
__device__ __align__(16) float g_kproj[SR * HH * DD];
__device__ __align__(16) float g_vproj[SR * HH * DD];
__device__ __align__(16) float g_ktil [HH * SR * DD];
__device__ __align__(16) float g_vtil [HH * SR * DD];
__device__ __align__(16) float g_span [NQ * DD];
__device__ __align__(16) float g_P    [NM * HH * JR * RR];
__device__ __align__(16) float g_ctx  [NQ * DD];
__device__ __align__(16) float g_cat  [NQ * 2 * DD];
__device__ __align__(16) float g_h1   [NQ * 2 * DD];
__device__ __align__(16) float g_f2   [NQ * DD];
__device__ __align__(16) float g_pool [NM * DD];
__device__ __align__(16) float g_t    [NM * DD];
// rounded operand copies
__device__ __align__(16) float g_encr [16 * 49 * 2048];
__device__ __align__(16) float g_Wal  [2048 * 768];
__device__ __align__(16) float g_Wq   [768 * 6144];
__device__ __align__(16) float g_Wk   [768 * 6144];
__device__ __align__(16) float g_Wv   [768 * 6144];
__device__ __align__(16) float g_Wfc  [6144 * 768];
__device__ __align__(16) float g_Wa1  [1536 * 1536];
__device__ __align__(16) float g_Wa2  [1536 * 768];
__device__ __align__(16) float g_Wd   [768 * 768];

// ---------------- tf32 helpers ----------------
__device__ __forceinline__ float rtf(float x) {
    uint32_t u;
    asm("cvt.rna.tf32.f32 %0, %1;" : "=r"(u) : "f"(x));
    return __uint_as_float(u);
}

__device__ __forceinline__ void mma8(float* c, const uint32_t* a, const uint32_t* b) {
    asm volatile(
        "mma.sync.aligned.m16n8k8.row.col.f32.tf32.tf32.f32 "
        "{%0,%1,%2,%3},{%4,%5,%6,%7},{%8,%9},{%0,%1,%2,%3};"
        : "+f"(c[0]), "+f"(c[1]), "+f"(c[2]), "+f"(c[3])
        : "r"(a[0]), "r"(a[1]), "r"(a[2]), "r"(a[3]), "r"(b[0]), "r"(b[1]));
}

__device__ __forceinline__ void cpa16(uint32_t saddr, const void* g) {
    asm volatile("cp.async.ca.shared.global [%0], [%1], 16;\n" :: "r"(saddr), "l"(g));
}
__device__ __forceinline__ void cpa_commit() {
    asm volatile("cp.async.commit_group;\n");
}
template<int N>
__device__ __forceinline__ void cpa_wait() {
    asm volatile("cp.async.wait_group %0;\n" :: "n"(N));
}

// ---------------- round pass ----------------
struct RJob { const float4* src; float4* dst; int n4; };
struct RJobs { RJob j[9]; };

__global__ void round9(RJobs jobs) {
    RJob jb = jobs.j[blockIdx.y];
    for (int i = blockIdx.x * blockDim.x + threadIdx.x; i < jb.n4;
         i += gridDim.x * blockDim.x) {
        float4 v = jb.src[i];
        v.x = rtf(v.x); v.y = rtf(v.y); v.z = rtf(v.z); v.w = rtf(v.w);
        jb.dst[i] = v;
    }
}

// ---------------- TF32 tensor-core GEMM, cp.async multistage -----------------
// Inputs MUST already be tf32-valued fp32 (pre-rounded). 128x128 tile, BK=8,
// NS-stage cp.async pipeline, 256 threads (8 warps of 64x32). N % 128 == 0,
// K % 8 == 0; M bounds-checked (rows clamped; garbage rows never stored).
// TRANSB: B element (k,n) = B[n*ldb + k]. ROUND: round output to tf32.
template<int ACT, bool TRANSB, int ROUND>
__global__ __launch_bounds__(256, 2)
void gemmtf(const float* __restrict__ A, const float* __restrict__ B,
            const float* __restrict__ bias, float* __restrict__ C,
            int M, int N, int K, int lda, int ldb, int ldc,
            long long aBS, long long bBS, long long cBS)
{
    constexpr int NS = TRANSB ? 3 : 4;
    constexpr int BS_U32 = TRANSB ? (128 * 12) : (8 * 136);

    A += (long long)blockIdx.z * aBS;
    B += (long long)blockIdx.z * bBS;
    C += (long long)blockIdx.z * cBS;

    __shared__ uint32_t As[NS][128 * 12];
    __shared__ uint32_t Bs[NS][BS_U32];

    const int tid = threadIdx.x;
    const int warp = tid >> 5, lane = tid & 31;
    const int g = lane >> 2, tig = lane & 3;
    const int wm = warp & 1, wn = warp >> 1;       // 2 x 4 warps: 64 x 32 each
    const int bm = blockIdx.y * 128, bn = blockIdx.x * 128;

    // loader coords
    const int la_m = tid >> 1, la_h = tid & 1;           // A: row, 16B-half
    const int lb_k = tid >> 5, lb_n4 = tid & 31;         // B non-trans
    const int lt_n = tid >> 1, lt_h = tid & 1;           // B trans

    const int a_gm = min(bm + la_m, M - 1);
    const float* a_src_base = A + (long long)a_gm * lda + la_h * 4;
    const float* b_src_nt = B + (long long)lb_k * ldb + bn + lb_n4 * 4;
    const float* b_src_t  = B + (long long)(bn + lt_n) * ldb + lt_h * 4;

    float acc[4][4][4];
    #pragma unroll
    for (int mt = 0; mt < 4; mt++)
        #pragma unroll
        for (int nt = 0; nt < 4; nt++)
            #pragma unroll
            for (int i = 0; i < 4; i++) acc[mt][nt][i] = 0.f;

    const int Ktiles = K >> 3;

    auto load_stage = [&](int s, int kt) {
        uint32_t sa = (uint32_t)__cvta_generic_to_shared(
            &As[s][la_m * 12 + la_h * 4]);
        cpa16(sa, a_src_base + kt * 8);
        if (!TRANSB) {
            uint32_t sb = (uint32_t)__cvta_generic_to_shared(
                &Bs[s][lb_k * 136 + lb_n4 * 4]);
            cpa16(sb, b_src_nt + (long long)kt * 8 * ldb);
        } else {
            uint32_t sb = (uint32_t)__cvta_generic_to_shared(
                &Bs[s][lt_n * 12 + lt_h * 4]);
            cpa16(sb, b_src_t + kt * 8);
        }
    };

    // prologue: NS-1 stages in flight
    #pragma unroll
    for (int t = 0; t < NS - 1; t++) { load_stage(t, t); cpa_commit(); }

    for (int kt = 0; kt < Ktiles; kt++) {
        cpa_wait<NS - 2>();
        __syncthreads();

        // issue the next stage (overlaps with compute below)
        int nk = kt + NS - 1;
        if (nk < Ktiles) load_stage(nk % NS, nk);
        cpa_commit();

        const int s = kt % NS;
        uint32_t af[4][4], bf[4][2];
        #pragma unroll
        for (int mt = 0; mt < 4; mt++) {
            int r = wm * 64 + mt * 16 + g;
            const uint32_t* p = &As[s][r * 12];
            af[mt][0] = p[tig];
            af[mt][1] = p[8 * 12 + tig];
            af[mt][2] = p[tig + 4];
            af[mt][3] = p[8 * 12 + tig + 4];
        }
        #pragma unroll
        for (int nt = 0; nt < 4; nt++) {
            int c = wn * 32 + nt * 8 + g;
            if (!TRANSB) {
                bf[nt][0] = Bs[s][tig * 136 + c];
                bf[nt][1] = Bs[s][(tig + 4) * 136 + c];
            } else {
                bf[nt][0] = Bs[s][c * 12 + tig];
                bf[nt][1] = Bs[s][c * 12 + tig + 4];
            }
        }
        #pragma unroll
        for (int mt = 0; mt < 4; mt++)
            #pragma unroll
            for (int nt = 0; nt < 4; nt++)
                mma8(acc[mt][nt], af[mt], bf[nt]);
        __syncthreads();
    }

    // epilogue
    #pragma unroll
    for (int mt = 0; mt < 4; mt++) {
        int r0 = bm + wm * 64 + mt * 16 + g;
        int r1 = r0 + 8;
        #pragma unroll
        for (int nt = 0; nt < 4; nt++) {
            int c = bn + wn * 32 + nt * 8 + 2 * tig;
            float b0 = bias ? bias[c] : 0.f;
            float b1 = bias ? bias[c + 1] : 0.f;
            float v0 = acc[mt][nt][0] + b0, v1 = acc[mt][nt][1] + b1;
            float v2 = acc[mt][nt][2] + b0, v3 = acc[mt][nt][3] + b1;
            if (ACT == 1) { v0 = tanhf(v0); v1 = tanhf(v1); v2 = tanhf(v2); v3 = tanhf(v3); }
            if (ROUND) { v0 = rtf(v0); v1 = rtf(v1); v2 = rtf(v2); v3 = rtf(v3); }
            if (r0 < M) *(float2*)(C + (long long)r0 * ldc + c) = make_float2(v0, v1);
            if (r1 < M) *(float2*)(C + (long long)r1 * ldc + c) = make_float2(v2, v3);
        }
    }
}

// ---------------- span gather (raw -> span, rounded -> cat left) -----------
__global__ void gather_kernel(const float* __restrict__ seq,
                              const int* __restrict__ starts,
                              float* __restrict__ out, float* __restrict__ cat)
{
    int sq = blockIdx.x;
    int s = sq / JR, q = sq - s * JR;
    int gstart = starts[s] + (s >> 3) * LSEQ;
    int idx = min(gstart + q, NB * LSEQ - 1);
    const float4* src = (const float4*)(seq + (long long)idx * DD);
    float4* dst = (float4*)(out + (long long)sq * DD);
    float4* dst2 = (float4*)(cat + (long long)sq * 2 * DD);
    for (int i = threadIdx.x; i < DD / 4; i += blockDim.x) {
        float4 v = src[i];
        dst[i] = v;
        float4 r;
        r.x = rtf(v.x); r.y = rtf(v.y); r.z = rtf(v.z); r.w = rtf(v.w);
        dst2[i] = r;
    }
}

// ---------------- attention logits + softmax ------------------------------
__global__ __launch_bounds__(256)
void attn_kernel(const float* __restrict__ span, const float* __restrict__ ktil,
                 float* __restrict__ P)
{
    int h = blockIdx.x;
    int s = blockIdx.y;
    int ns = s >> 3;
    __shared__ float sa[JR][33];
    __shared__ float sb[RR][33];
    __shared__ float sl[JR * RR];

    int tid = threadIdx.x;
    float acc[6] = {0.f, 0.f, 0.f, 0.f, 0.f, 0.f};
    int qi[6], ri[6];
    #pragma unroll
    for (int i = 0; i < 6; i++) {
        int p = tid + 256 * i;
        qi[i] = p / RR;
        ri[i] = p - qi[i] * RR;
    }

    const float* sp = span + (long long)s * JR * DD;
    const float* kp = ktil + (long long)(h * SR + ns * RR) * DD;

    for (int k0 = 0; k0 < DD; k0 += 32) {
        if (tid < 240) {
            int row = tid >> 3, c4 = (tid & 7) << 2;
            float4 v = *(const float4*)(sp + (long long)row * DD + k0 + c4);
            sa[row][c4] = v.x; sa[row][c4 + 1] = v.y;
            sa[row][c4 + 2] = v.z; sa[row][c4 + 3] = v.w;
        }
        for (int i = tid; i < RR * 8; i += 256) {
            int row = i >> 3, c4 = (i & 7) << 2;
            float4 v = *(const float4*)(kp + (long long)row * DD + k0 + c4);
            sb[row][c4] = v.x; sb[row][c4 + 1] = v.y;
            sb[row][c4 + 2] = v.z; sb[row][c4 + 3] = v.w;
        }
        __syncthreads();
        #pragma unroll
        for (int i = 0; i < 6; i++) {
            if (tid + 256 * i < JR * RR) {
                float a = 0.f;
                #pragma unroll
                for (int kk = 0; kk < 32; kk++)
                    a += sa[qi[i]][kk] * sb[ri[i]][kk];
                acc[i] += a;
            }
        }
        __syncthreads();
    }

    const float scale = rsqrtf((float)DD);
    #pragma unroll
    for (int i = 0; i < 6; i++) {
        int p = tid + 256 * i;
        if (p < JR * RR) sl[p] = acc[i] * scale;
    }
    __syncthreads();

    int warp = tid >> 5, lane = tid & 31;
    for (int q = warp; q < JR; q += 8) {
        float v0 = sl[q * RR + lane];
        float v1 = (lane + 32 < RR) ? sl[q * RR + lane + 32] : -3.0e38f;
        float m = fmaxf(v0, v1);
        #pragma unroll
        for (int o = 16; o; o >>= 1) m = fmaxf(m, __shfl_xor_sync(0xffffffffu, m, o));
        float e0 = expf(v0 - m);
        float e1 = (lane + 32 < RR) ? expf(v1 - m) : 0.f;
        float sum = e0 + e1;
        #pragma unroll
        for (int o = 16; o; o >>= 1) sum += __shfl_xor_sync(0xffffffffu, sum, o);
        float inv = 1.f / sum;
        float* Pr = P + (long long)((s * HH + h) * JR + q) * RR;
        Pr[lane] = e0 * inv;
        if (lane + 32 < RR) Pr[lane + 32] = e1 * inv;
    }
}

// ---------------- attention-value + residual ------------------------------
__global__ __launch_bounds__(256)
void av_kernel(const float* __restrict__ P, const float* __restrict__ vtil,
               const float* __restrict__ span, float* __restrict__ ctx)
{
    int s = blockIdx.y;
    int o = blockIdx.x * 256 + threadIdx.x;
    int ns = s >> 3;
    __shared__ float Ps[HH * JR * RR];
    for (int i = threadIdx.x; i < HH * JR * RR; i += 256)
        Ps[i] = P[(long long)s * HH * JR * RR + i];
    __syncthreads();

    float acc[JR];
    #pragma unroll
    for (int q = 0; q < JR; q++) acc[q] = 0.f;

    for (int h = 0; h < HH; h++) {
        const float* vp = vtil + (long long)(h * SR + ns * RR) * DD + o;
        const float* pp = Ps + h * JR * RR;
        for (int r = 0; r < RR; r++) {
            float v = vp[(long long)r * DD];
            #pragma unroll
            for (int q = 0; q < JR; q++)
                acc[q] += pp[q * RR + r] * v;
        }
    }
    const float* sp = span + (long long)s * JR * DD + o;
    float* cp = ctx + (long long)s * JR * DD + o;
    #pragma unroll
    for (int q = 0; q < JR; q++)
        cp[(long long)q * DD] = acc[q] + sp[(long long)q * DD];
}

// ---------------- layernorm (strided rounded output into cat) --------------
__global__ __launch_bounds__(256)
void ln_kernel(const float* __restrict__ X, const float* __restrict__ g,
               const float* __restrict__ b, float* __restrict__ Y, int ostride)
{
    int r = blockIdx.x;
    int t = threadIdx.x;
    const float* x = X + (long long)r * DD;
    float v0 = x[t], v1 = x[t + 256], v2 = x[t + 512];
    __shared__ float red[8];

    float s = v0 + v1 + v2;
    #pragma unroll
    for (int o = 16; o; o >>= 1) s += __shfl_xor_sync(0xffffffffu, s, o);
    if ((t & 31) == 0) red[t >> 5] = s;
    __syncthreads();
    if (t == 0) { float z = 0.f; for (int i = 0; i < 8; i++) z += red[i]; red[0] = z; }
    __syncthreads();
    float mu = red[0] * (1.0f / DD);
    __syncthreads();

    float d0 = v0 - mu, d1 = v1 - mu, d2 = v2 - mu;
    float ss = d0 * d0 + d1 * d1 + d2 * d2;
    #pragma unroll
    for (int o = 16; o; o >>= 1) ss += __shfl_xor_sync(0xffffffffu, ss, o);
    if ((t & 31) == 0) red[t >> 5] = ss;
    __syncthreads();
    if (t == 0) { float z = 0.f; for (int i = 0; i < 8; i++) z += red[i]; red[0] = z; }
    __syncthreads();
    float inv = rsqrtf(red[0] * (1.0f / DD) + 1e-5f);

    float* y = Y + (long long)r * ostride;
    y[t]       = rtf(d0 * inv * g[t]       + b[t]);
    y[t + 256] = rtf(d1 * inv * g[t + 256] + b[t + 256]);
    y[t + 512] = rtf(d2 * inv * g[t + 512] + b[t + 512]);
}

// ---------------- unary score + masked softmax + pooling --------------------
__global__ __launch_bounds__(256)
void pool_kernel(const float* __restrict__ F2, const float* __restrict__ W_un,
                 const float* __restrict__ b_un, const int* __restrict__ starts,
                 const int* __restrict__ ends, float* __restrict__ pooled)
{
    int s = blockIdx.x;
    __shared__ float sc[JR];
    __shared__ float pr[32];
    int tid = threadIdx.x, warp = tid >> 5, lane = tid & 31;

    for (int q = warp; q < JR; q += 8) {
        const float* row = F2 + (long long)(s * JR + q) * DD;
        float acc = 0.f;
        for (int k = lane; k < DD; k += 32) acc += row[k] * W_un[k];
        #pragma unroll
        for (int o = 16; o; o >>= 1) acc += __shfl_xor_sync(0xffffffffu, acc, o);
        if (lane == 0) sc[q] = acc + b_un[0];
    }
    __syncthreads();

    if (tid < 32) {
        int width = ends[s] - starts[s] + 1;
        float v = -3.0e38f;
        if (tid < JR) {
            v = sc[tid];
            if (tid >= width) v += -10000.0f;
        }
        float m = v;
        #pragma unroll
        for (int o = 16; o; o >>= 1) m = fmaxf(m, __shfl_xor_sync(0xffffffffu, m, o));
        float e = (tid < JR) ? expf(v - m) : 0.f;
        float sum = e;
        #pragma unroll
        for (int o = 16; o; o >>= 1) sum += __shfl_xor_sync(0xffffffffu, sum, o);
        pr[tid] = (tid < JR) ? e / sum : 0.f;
    }
    __syncthreads();

    for (int o = tid; o < DD; o += 256) {
        float acc = 0.f;
        #pragma unroll
        for (int q = 0; q < JR; q++)
            acc += pr[q] * F2[(long long)(s * JR + q) * DD + o];
        pooled[(long long)s * DD + o] = rtf(acc);
    }
}

// ---------------- classifier ------------------------------------------------
__global__ void cls_kernel(const float* __restrict__ T, const float* __restrict__ Wc,
                           const float* __restrict__ bc, float* __restrict__ out)
{
    int s = blockIdx.x;
    int c = threadIdx.x >> 5, lane = threadIdx.x & 31;
    const float* t = T + (long long)s * DD;
    float acc = 0.f;
    for (int k = lane; k < DD; k += 32) acc += t[k] * Wc[k * 4 + c];
    #pragma unroll
    for (int o = 16; o; o >>= 1) acc += __shfl_xor_sync(0xffffffffu, acc, o);
    if (lane == 0) out[s * 4 + c] = acc + bc[c];
}

// ---------------- launcher --------------------------------------------------
extern "C" void kernel_launch(void* const* d_in, const int* in_sizes, int n_in,
                              void* d_out, int out_size)
{
    const float* enc_img  = (const float*)d_in[0];
    const float* seq      = (const float*)d_in[1];
    const int*   starts   = (const int*)d_in[3];
    const int*   ends     = (const int*)d_in[4];
    const float* W_align  = (const float*)d_in[5];
    const float* b_align  = (const float*)d_in[6];
    const float* Wq       = (const float*)d_in[7];
    const float* Wk       = (const float*)d_in[8];
    const float* Wv       = (const float*)d_in[9];
    const float* Wfc      = (const float*)d_in[10];
    const float* ln_g     = (const float*)d_in[11];
    const float* ln_b     = (const float*)d_in[12];
    const float* W_a1     = (const float*)d_in[13];
    const float* b_a1     = (const float*)d_in[14];
    const float* W_a2     = (const float*)d_in[15];
    const float* b_a2     = (const float*)d_in[16];
    const float* W_un     = (const float*)d_in[17];
    const float* b_un     = (const float*)d_in[18];
    const float* W_dense  = (const float*)d_in[19];
    const float* b_dense  = (const float*)d_in[20];
    const float* W_cls    = (const float*)d_in[21];
    const float* b_cls    = (const float*)d_in[22];
    float* out = (float*)d_out;

    float *res, *kproj, *vproj, *ktil, *vtil, *span, *P, *ctx, *cat, *h1, *f2, *pool, *tb;
    float *encr, *wal, *wq, *wk, *wv, *wfc, *wa1, *wa2, *wd;
    cudaGetSymbolAddress((void**)&res,   g_res);
    cudaGetSymbolAddress((void**)&kproj, g_kproj);
    cudaGetSymbolAddress((void**)&vproj, g_vproj);
    cudaGetSymbolAddress((void**)&ktil,  g_ktil);
    cudaGetSymbolAddress((void**)&vtil,  g_vtil);
    cudaGetSymbolAddress((void**)&span,  g_span);
    cudaGetSymbolAddress((void**)&P,     g_P);
    cudaGetSymbolAddress((void**)&ctx,   g_ctx);
    cudaGetSymbolAddress((void**)&cat,   g_cat);
    cudaGetSymbolAddress((void**)&h1,    g_h1);
    cudaGetSymbolAddress((void**)&f2,    g_f2);
    cudaGetSymbolAddress((void**)&pool,  g_pool);
    cudaGetSymbolAddress((void**)&tb,    g_t);
    cudaGetSymbolAddress((void**)&encr,  g_encr);
    cudaGetSymbolAddress((void**)&wal,   g_Wal);
    cudaGetSymbolAddress((void**)&wq,    g_Wq);
    cudaGetSymbolAddress((void**)&wk,    g_Wk);
    cudaGetSymbolAddress((void**)&wv,    g_Wv);
    cudaGetSymbolAddress((void**)&wfc,   g_Wfc);
    cudaGetSymbolAddress((void**)&wa1,   g_Wa1);
    cudaGetSymbolAddress((void**)&wa2,   g_Wa2);
    cudaGetSymbolAddress((void**)&wd,    g_Wd);

    // -1) pre-round all GEMM operand matrices to exact tf32 values
    RJobs jobs;
    jobs.j[0] = { (const float4*)enc_img, (float4*)encr, 16 * 49 * 2048 / 4 };
    jobs.j[1] = { (const float4*)W_align, (float4*)wal,  2048 * 768 / 4 };
    jobs.j[2] = { (const float4*)Wq,      (float4*)wq,   768 * 6144 / 4 };
    jobs.j[3] = { (const float4*)Wk,      (float4*)wk,   768 * 6144 / 4 };
    jobs.j[4] = { (const float4*)Wv,      (float4*)wv,   768 * 6144 / 4 };
    jobs.j[5] = { (const float4*)Wfc,     (float4*)wfc,  6144 * 768 / 4 };
    jobs.j[6] = { (const float4*)W_a1,    (float4*)wa1,  1536 * 1536 / 4 };
    jobs.j[7] = { (const float4*)W_a2,    (float4*)wa2,  1536 * 768 / 4 };
    jobs.j[8] = { (const float4*)W_dense, (float4*)wd,   768 * 768 / 4 };
    round9<<<dim3(1024, 9), 256>>>(jobs);

    // 0) res = enc_img @ W_align + b_align       [784,768]  (rounded out)
    gemmtf<0, false, 1><<<dim3(6, 7, 1), 256>>>(
        encr, wal, b_align, res, SR, 768, 2048, 2048, 768, 768, 0, 0, 0);
    // 1) kproj = res @ Wk                         [784,6144] (rounded out)
    gemmtf<0, false, 1><<<dim3(48, 7, 1), 256>>>(
        res, wk, nullptr, kproj, SR, 6144, 768, 768, 6144, 6144, 0, 0, 0);
    // 2) vproj = res @ Wv                         [784,6144] (rounded out)
    gemmtf<0, false, 1><<<dim3(48, 7, 1), 256>>>(
        res, wv, nullptr, vproj, SR, 6144, 768, 768, 6144, 6144, 0, 0, 0);
    // 3) ktil_h = kproj_h @ Wq_h^T (batched)      [8,784,768] (raw out)
    gemmtf<0, true, 0><<<dim3(6, 7, HH), 256>>>(
        kproj, wq, nullptr, ktil, SR, 768, 768, 6144, 6144, 768,
        768LL, 768LL, (long long)SR * 768);
    // 4) vtil_h = vproj_h @ Wfc_h (batched)       [8,784,768] (raw out)
    gemmtf<0, false, 0><<<dim3(6, 7, HH), 256>>>(
        vproj, wfc, nullptr, vtil, SR, 768, 768, 6144, 768, 768,
        768LL, 768LL * 768LL, (long long)SR * 768);
    // 5) span gather (raw span, rounded cat-left)
    gather_kernel<<<NQ, 192>>>(seq, starts, span, cat);
    // 6) attention logits + softmax -> P (fp32)
    attn_kernel<<<dim3(HH, NM), 256>>>(span, ktil, P);
    // 7) AV + residual -> ctx (fp32)
    av_kernel<<<dim3(3, NM), 256>>>(P, vtil, span, ctx);
    // 8) layernorm -> cat right half (rounded, stride 1536)
    ln_kernel<<<NQ, 256>>>(ctx, ln_g, ln_b, cat + DD, 2 * DD);
    // 10) h1 = tanh(cat @ W_a1 + b_a1)            [3840,1536] (rounded out)
    gemmtf<1, false, 1><<<dim3(12, 30, 1), 256>>>(
        cat, wa1, b_a1, h1, NQ, 1536, 1536, 1536, 1536, 1536, 0, 0, 0);
    // 11) f2 = h1 @ W_a2 + b_a2                   [3840,768] (raw out)
    gemmtf<0, false, 0><<<dim3(6, 30, 1), 256>>>(
        h1, wa2, b_a2, f2, NQ, 768, 1536, 1536, 768, 768, 0, 0, 0);
    // 12) score + masked softmax + pooled (rounded) [128,768]
    pool_kernel<<<NM, 256>>>(f2, W_un, b_un, starts, ends, pool);
    // 13) t = tanh(pool @ W_dense + b_dense)      [128,768] (raw out)
    gemmtf<1, false, 0><<<dim3(6, 1, 1), 256>>>(
        pool, wd, b_dense, tb, NM, 768, 768, 768, 768, 768, 0, 0, 0);
    // 14) logits = t @ W_cls + b_cls              [128,4]
    cls_kernel<<<NM, 128>>>(tb, W_cls, b_cls, out);
}

// round 7
// speedup vs baseline: 2.6245x; 1.0855x over previous
#include <cuda_runtime.h>
#include <cuda_bf16.h>
#include <math.h>
#include <stdint.h>

// Problem constants
#define NB 16
#define LSEQ 128
#define DD 768
#define HH 8
#define JR 30
#define RR 49
#define NM 128       // N*M spans
#define NQ 3840      // NM*JR rows
#define SR 784       // NB*RR rows

// ---------------- scratch ----------------
__device__ __align__(16) float g_res   [SR * DD];
__device__ __align__(16) float g_kvproj[SR * 2 * HH * DD];   // [784,12288] = kproj|vproj
__device__ __align__(16) float g_ktil  [HH * SR * DD];
__device__ __align__(16) float g_vtil  [HH * SR * DD];
__device__ __align__(16) float g_span  [NQ * DD];
__device__ __align__(16) float g_P     [NM * HH * JR * RR];
__device__ __align__(16) float g_ctx   [NQ * DD];
__device__ __align__(16) float g_cat   [NQ * 2 * DD];
__device__ __align__(16) float g_h1    [NQ * 2 * DD];
__device__ __align__(16) float g_f2    [NQ * DD];
__device__ __align__(16) float g_pool  [NM * DD];
__device__ __align__(16) float g_t     [NM * DD];
// rounded operand copies
__device__ __align__(16) float g_encr  [16 * 49 * 2048];
__device__ __align__(16) float g_Wal   [2048 * 768];
__device__ __align__(16) float g_Wkv   [768 * 12288];        // Wk | Wv packed on N
__device__ __align__(16) float g_WqT   [HH * 768 * 768];     // per-head transposed Wq
__device__ __align__(16) float g_Wfc   [6144 * 768];
__device__ __align__(16) float g_Wa1   [1536 * 1536];
__device__ __align__(16) float g_Wa2   [1536 * 768];
__device__ __align__(16) float g_Wd    [768 * 768];

// ---------------- tf32 helpers ----------------
__device__ __forceinline__ float rtf(float x) {
    uint32_t u;
    asm("cvt.rna.tf32.f32 %0, %1;" : "=r"(u) : "f"(x));
    return __uint_as_float(u);
}

__device__ __forceinline__ void mma8(float* c, const uint32_t* a, const uint32_t* b) {
    asm volatile(
        "mma.sync.aligned.m16n8k8.row.col.f32.tf32.tf32.f32 "
        "{%0,%1,%2,%3},{%4,%5,%6,%7},{%8,%9},{%0,%1,%2,%3};"
        : "+f"(c[0]), "+f"(c[1]), "+f"(c[2]), "+f"(c[3])
        : "r"(a[0]), "r"(a[1]), "r"(a[2]), "r"(a[3]), "r"(b[0]), "r"(b[1]));
}

__device__ __forceinline__ void cpa16(uint32_t saddr, const void* g) {
    asm volatile("cp.async.ca.shared.global [%0], [%1], 16;\n" :: "r"(saddr), "l"(g));
}
__device__ __forceinline__ void cpa_commit() {
    asm volatile("cp.async.commit_group;\n");
}
template<int N>
__device__ __forceinline__ void cpa_wait() {
    asm volatile("cp.async.wait_group %0;\n" :: "n"(N));
}

// ---------------- round / pack pass ----------------
struct RJob { const float4* src; float4* dst; int n4; int row4; int stride4; };
struct RJobs { RJob j[8]; };

__global__ void round8(RJobs jobs) {
    RJob jb = jobs.j[blockIdx.y];
    for (int i = blockIdx.x * blockDim.x + threadIdx.x; i < jb.n4;
         i += gridDim.x * blockDim.x) {
        float4 v = jb.src[i];
        v.x = rtf(v.x); v.y = rtf(v.y); v.z = rtf(v.z); v.w = rtf(v.w);
        int row = i / jb.row4;
        int col = i - row * jb.row4;
        jb.dst[(long long)row * jb.stride4 + col] = v;
    }
}

// Wq [768, 6144] -> WqT [8][768][768]: WqT[h][d][j] = rtf(Wq[j][h*768+d])
__global__ void transposeWq(const float* __restrict__ Wq, float* __restrict__ WqT) {
    __shared__ float t[32][33];
    int h = blockIdx.z;
    int j0 = blockIdx.y * 32, d0 = blockIdx.x * 32;
    int tx = threadIdx.x, ty = threadIdx.y;   // 32 x 8
    #pragma unroll
    for (int dy = 0; dy < 32; dy += 8)
        t[ty + dy][tx] = Wq[(long long)(j0 + ty + dy) * 6144 + h * 768 + d0 + tx];
    __syncthreads();
    #pragma unroll
    for (int dy = 0; dy < 32; dy += 8)
        WqT[((long long)h * 768 + d0 + ty + dy) * 768 + j0 + tx] = rtf(t[tx][ty + dy]);
}

// ---------------- TF32 tensor-core GEMM, cp.async multistage -----------------
// BK=16 per stage (2 x k8 sub-blocks), NS=3 stages, ONE barrier per stage.
// 128x128 CTA tile, 256 threads (8 warps of 64x32). N%128==0, K%16==0,
// M bounds-checked. Inputs must be tf32-valued fp32. Dynamic smem: 62976 B.
#define STAGE_U32 5248              // 2*128*12 (A) + 2*8*136 (B)
#define GEMM_SMEM (3 * STAGE_U32 * 4)

template<int ACT, int ROUND>
__global__ __launch_bounds__(256, 2)
void gemmtf(const float* __restrict__ A, const float* __restrict__ B,
            const float* __restrict__ bias, float* __restrict__ C,
            int M, int N, int K, int lda, int ldb, int ldc,
            long long aBS, long long bBS, long long cBS)
{
    constexpr int NS = 3;
    extern __shared__ uint32_t sm[];

    A += (long long)blockIdx.z * aBS;
    B += (long long)blockIdx.z * bBS;
    C += (long long)blockIdx.z * cBS;

    const int tid = threadIdx.x;
    const int warp = tid >> 5, lane = tid & 31;
    const int g = lane >> 2, tig = lane & 3;
    const int wm = warp & 1, wn = warp >> 1;     // 2x4 warps: 64x32 each
    const int bm = blockIdx.y * 128, bn = blockIdx.x * 128;

    // loader coords
    const int la_row = tid >> 1, la_half = tid & 1;   // A: row, 16B half of 8-float slice
    const int lb_k = tid >> 5, lb_n4 = tid & 31;      // B: k row, 16B col group

    const float* aP = A + (long long)min(bm + la_row, M - 1) * lda + la_half * 4;
    const float* bP = B + (long long)lb_k * ldb + bn + lb_n4 * 4;

    const uint32_t smbase = (uint32_t)__cvta_generic_to_shared(sm);
    // stage layout: [A sub0 1536][A sub1 1536][B sub0 1088][B sub1 1088]
    const uint32_t a_off = (la_row * 12 + la_half * 4) * 4;
    const uint32_t b_off = (lb_k * 136 + lb_n4 * 4) * 4;

    float acc[4][4][4];
    #pragma unroll
    for (int mt = 0; mt < 4; mt++)
        #pragma unroll
        for (int nt = 0; nt < 4; nt++)
            #pragma unroll
            for (int i = 0; i < 4; i++) acc[mt][nt][i] = 0.f;

    const int Kt = K >> 4;

    auto load_stage = [&](int buf, int kt) {
        uint32_t sb = smbase + buf * (STAGE_U32 * 4);
        const float* ak = aP + kt * 16;
        const float* bk = bP + (long long)kt * 16 * ldb;
        cpa16(sb + a_off,            ak);
        cpa16(sb + 1536 * 4 + a_off, ak + 8);
        cpa16(sb + 3072 * 4 + b_off, bk);
        cpa16(sb + 4160 * 4 + b_off, bk + (long long)8 * ldb);
    };

    // prologue: NS-1 stages in flight
    load_stage(0, 0); cpa_commit();
    load_stage(1, 1); cpa_commit();

    for (int kt = 0; kt < Kt; kt++) {
        cpa_wait<NS - 2>();
        __syncthreads();     // stage kt visible; buffer (kt-1)%NS free for reuse

        const int buf = kt % NS;
        const uint32_t* As = sm + buf * STAGE_U32;
        const uint32_t* Bs = As + 3072;

        #pragma unroll
        for (int s2 = 0; s2 < 2; s2++) {
            const uint32_t* Ap = As + s2 * 1536;
            const uint32_t* Bp = Bs + s2 * 1088;
            uint32_t af[4][4], bf[4][2];
            #pragma unroll
            for (int mt = 0; mt < 4; mt++) {
                const uint32_t* p = Ap + (wm * 64 + mt * 16 + g) * 12;
                af[mt][0] = p[tig];
                af[mt][1] = p[96 + tig];
                af[mt][2] = p[tig + 4];
                af[mt][3] = p[96 + tig + 4];
            }
            #pragma unroll
            for (int nt = 0; nt < 4; nt++) {
                int c = wn * 32 + nt * 8 + g;
                bf[nt][0] = Bp[tig * 136 + c];
                bf[nt][1] = Bp[(tig + 4) * 136 + c];
            }
            #pragma unroll
            for (int mt = 0; mt < 4; mt++)
                #pragma unroll
                for (int nt = 0; nt < 4; nt++)
                    mma8(acc[mt][nt], af[mt], bf[nt]);
        }

        // issue next stage into buffer (kt-1)%NS (freed by this iteration's barrier)
        int nk = kt + NS - 1;
        if (nk < Kt) load_stage(nk % NS, nk);
        cpa_commit();
    }

    // epilogue
    #pragma unroll
    for (int mt = 0; mt < 4; mt++) {
        int r0 = bm + wm * 64 + mt * 16 + g;
        int r1 = r0 + 8;
        #pragma unroll
        for (int nt = 0; nt < 4; nt++) {
            int c = bn + wn * 32 + nt * 8 + 2 * tig;
            float b0 = bias ? bias[c] : 0.f;
            float b1 = bias ? bias[c + 1] : 0.f;
            float v0 = acc[mt][nt][0] + b0, v1 = acc[mt][nt][1] + b1;
            float v2 = acc[mt][nt][2] + b0, v3 = acc[mt][nt][3] + b1;
            if (ACT == 1) { v0 = tanhf(v0); v1 = tanhf(v1); v2 = tanhf(v2); v3 = tanhf(v3); }
            if (ROUND) { v0 = rtf(v0); v1 = rtf(v1); v2 = rtf(v2); v3 = rtf(v3); }
            if (r0 < M) *(float2*)(C + (long long)r0 * ldc + c) = make_float2(v0, v1);
            if (r1 < M) *(float2*)(C + (long long)r1 * ldc + c) = make_float2(v2, v3);
        }
    }
}

// ---------------- span gather (raw -> span, rounded -> cat left) -----------
__global__ void gather_kernel(const float* __restrict__ seq,
                              const int* __restrict__ starts,
                              float* __restrict__ out, float* __restrict__ cat)
{
    int sq = blockIdx.x;
    int s = sq / JR, q = sq - s * JR;
    int gstart = starts[s] + (s >> 3) * LSEQ;
    int idx = min(gstart + q, NB * LSEQ - 1);
    const float4* src = (const float4*)(seq + (long long)idx * DD);
    float4* dst = (float4*)(out + (long long)sq * DD);
    float4* dst2 = (float4*)(cat + (long long)sq * 2 * DD);
    for (int i = threadIdx.x; i < DD / 4; i += blockDim.x) {
        float4 v = src[i];
        dst[i] = v;
        float4 r;
        r.x = rtf(v.x); r.y = rtf(v.y); r.z = rtf(v.z); r.w = rtf(v.w);
        dst2[i] = r;
    }
}

// ---------------- attention logits + softmax ------------------------------
__global__ __launch_bounds__(256)
void attn_kernel(const float* __restrict__ span, const float* __restrict__ ktil,
                 float* __restrict__ P)
{
    int h = blockIdx.x;
    int s = blockIdx.y;
    int ns = s >> 3;
    __shared__ float sa[JR][33];
    __shared__ float sb[RR][33];
    __shared__ float sl[JR * RR];

    int tid = threadIdx.x;
    float acc[6] = {0.f, 0.f, 0.f, 0.f, 0.f, 0.f};
    int qi[6], ri[6];
    #pragma unroll
    for (int i = 0; i < 6; i++) {
        int p = tid + 256 * i;
        qi[i] = p / RR;
        ri[i] = p - qi[i] * RR;
    }

    const float* sp = span + (long long)s * JR * DD;
    const float* kp = ktil + (long long)(h * SR + ns * RR) * DD;

    for (int k0 = 0; k0 < DD; k0 += 32) {
        if (tid < 240) {
            int row = tid >> 3, c4 = (tid & 7) << 2;
            float4 v = *(const float4*)(sp + (long long)row * DD + k0 + c4);
            sa[row][c4] = v.x; sa[row][c4 + 1] = v.y;
            sa[row][c4 + 2] = v.z; sa[row][c4 + 3] = v.w;
        }
        for (int i = tid; i < RR * 8; i += 256) {
            int row = i >> 3, c4 = (i & 7) << 2;
            float4 v = *(const float4*)(kp + (long long)row * DD + k0 + c4);
            sb[row][c4] = v.x; sb[row][c4 + 1] = v.y;
            sb[row][c4 + 2] = v.z; sb[row][c4 + 3] = v.w;
        }
        __syncthreads();
        #pragma unroll
        for (int i = 0; i < 6; i++) {
            if (tid + 256 * i < JR * RR) {
                float a = 0.f;
                #pragma unroll
                for (int kk = 0; kk < 32; kk++)
                    a += sa[qi[i]][kk] * sb[ri[i]][kk];
                acc[i] += a;
            }
        }
        __syncthreads();
    }

    const float scale = rsqrtf((float)DD);
    #pragma unroll
    for (int i = 0; i < 6; i++) {
        int p = tid + 256 * i;
        if (p < JR * RR) sl[p] = acc[i] * scale;
    }
    __syncthreads();

    int warp = tid >> 5, lane = tid & 31;
    for (int q = warp; q < JR; q += 8) {
        float v0 = sl[q * RR + lane];
        float v1 = (lane + 32 < RR) ? sl[q * RR + lane + 32] : -3.0e38f;
        float m = fmaxf(v0, v1);
        #pragma unroll
        for (int o = 16; o; o >>= 1) m = fmaxf(m, __shfl_xor_sync(0xffffffffu, m, o));
        float e0 = expf(v0 - m);
        float e1 = (lane + 32 < RR) ? expf(v1 - m) : 0.f;
        float sum = e0 + e1;
        #pragma unroll
        for (int o = 16; o; o >>= 1) sum += __shfl_xor_sync(0xffffffffu, sum, o);
        float inv = 1.f / sum;
        float* Pr = P + (long long)((s * HH + h) * JR + q) * RR;
        Pr[lane] = e0 * inv;
        if (lane + 32 < RR) Pr[lane + 32] = e1 * inv;
    }
}

// ---------------- attention-value + residual ------------------------------
__global__ __launch_bounds__(256)
void av_kernel(const float* __restrict__ P, const float* __restrict__ vtil,
               const float* __restrict__ span, float* __restrict__ ctx)
{
    int s = blockIdx.y;
    int o = blockIdx.x * 256 + threadIdx.x;
    int ns = s >> 3;
    __shared__ float Ps[HH * JR * RR];
    for (int i = threadIdx.x; i < HH * JR * RR; i += 256)
        Ps[i] = P[(long long)s * HH * JR * RR + i];
    __syncthreads();

    float acc[JR];
    #pragma unroll
    for (int q = 0; q < JR; q++) acc[q] = 0.f;

    for (int h = 0; h < HH; h++) {
        const float* vp = vtil + (long long)(h * SR + ns * RR) * DD + o;
        const float* pp = Ps + h * JR * RR;
        for (int r = 0; r < RR; r++) {
            float v = vp[(long long)r * DD];
            #pragma unroll
            for (int q = 0; q < JR; q++)
                acc[q] += pp[q * RR + r] * v;
        }
    }
    const float* sp = span + (long long)s * JR * DD + o;
    float* cp = ctx + (long long)s * JR * DD + o;
    #pragma unroll
    for (int q = 0; q < JR; q++)
        cp[(long long)q * DD] = acc[q] + sp[(long long)q * DD];
}

// ---------------- layernorm (strided rounded output into cat) --------------
__global__ __launch_bounds__(256)
void ln_kernel(const float* __restrict__ X, const float* __restrict__ g,
               const float* __restrict__ b, float* __restrict__ Y, int ostride)
{
    int r = blockIdx.x;
    int t = threadIdx.x;
    const float* x = X + (long long)r * DD;
    float v0 = x[t], v1 = x[t + 256], v2 = x[t + 512];
    __shared__ float red[8];

    float s = v0 + v1 + v2;
    #pragma unroll
    for (int o = 16; o; o >>= 1) s += __shfl_xor_sync(0xffffffffu, s, o);
    if ((t & 31) == 0) red[t >> 5] = s;
    __syncthreads();
    if (t == 0) { float z = 0.f; for (int i = 0; i < 8; i++) z += red[i]; red[0] = z; }
    __syncthreads();
    float mu = red[0] * (1.0f / DD);
    __syncthreads();

    float d0 = v0 - mu, d1 = v1 - mu, d2 = v2 - mu;
    float ss = d0 * d0 + d1 * d1 + d2 * d2;
    #pragma unroll
    for (int o = 16; o; o >>= 1) ss += __shfl_xor_sync(0xffffffffu, ss, o);
    if ((t & 31) == 0) red[t >> 5] = ss;
    __syncthreads();
    if (t == 0) { float z = 0.f; for (int i = 0; i < 8; i++) z += red[i]; red[0] = z; }
    __syncthreads();
    float inv = rsqrtf(red[0] * (1.0f / DD) + 1e-5f);

    float* y = Y + (long long)r * ostride;
    y[t]       = rtf(d0 * inv * g[t]       + b[t]);
    y[t + 256] = rtf(d1 * inv * g[t + 256] + b[t + 256]);
    y[t + 512] = rtf(d2 * inv * g[t + 512] + b[t + 512]);
}

// ---------------- unary score + masked softmax + pooling --------------------
__global__ __launch_bounds__(256)
void pool_kernel(const float* __restrict__ F2, const float* __restrict__ W_un,
                 const float* __restrict__ b_un, const int* __restrict__ starts,
                 const int* __restrict__ ends, float* __restrict__ pooled)
{
    int s = blockIdx.x;
    __shared__ float sc[JR];
    __shared__ float pr[32];
    int tid = threadIdx.x, warp = tid >> 5, lane = tid & 31;

    for (int q = warp; q < JR; q += 8) {
        const float* row = F2 + (long long)(s * JR + q) * DD;
        float acc = 0.f;
        for (int k = lane; k < DD; k += 32) acc += row[k] * W_un[k];
        #pragma unroll
        for (int o = 16; o; o >>= 1) acc += __shfl_xor_sync(0xffffffffu, acc, o);
        if (lane == 0) sc[q] = acc + b_un[0];
    }
    __syncthreads();

    if (tid < 32) {
        int width = ends[s] - starts[s] + 1;
        float v = -3.0e38f;
        if (tid < JR) {
            v = sc[tid];
            if (tid >= width) v += -10000.0f;
        }
        float m = v;
        #pragma unroll
        for (int o = 16; o; o >>= 1) m = fmaxf(m, __shfl_xor_sync(0xffffffffu, m, o));
        float e = (tid < JR) ? expf(v - m) : 0.f;
        float sum = e;
        #pragma unroll
        for (int o = 16; o; o >>= 1) sum += __shfl_xor_sync(0xffffffffu, sum, o);
        pr[tid] = (tid < JR) ? e / sum : 0.f;
    }
    __syncthreads();

    for (int o = tid; o < DD; o += 256) {
        float acc = 0.f;
        #pragma unroll
        for (int q = 0; q < JR; q++)
            acc += pr[q] * F2[(long long)(s * JR + q) * DD + o];
        pooled[(long long)s * DD + o] = rtf(acc);
    }
}

// ---------------- classifier ------------------------------------------------
__global__ void cls_kernel(const float* __restrict__ T, const float* __restrict__ Wc,
                           const float* __restrict__ bc, float* __restrict__ out)
{
    int s = blockIdx.x;
    int c = threadIdx.x >> 5, lane = threadIdx.x & 31;
    const float* t = T + (long long)s * DD;
    float acc = 0.f;
    for (int k = lane; k < DD; k += 32) acc += t[k] * Wc[k * 4 + c];
    #pragma unroll
    for (int o = 16; o; o >>= 1) acc += __shfl_xor_sync(0xffffffffu, acc, o);
    if (lane == 0) out[s * 4 + c] = acc + bc[c];
}

// ---------------- launcher --------------------------------------------------
extern "C" void kernel_launch(void* const* d_in, const int* in_sizes, int n_in,
                              void* d_out, int out_size)
{
    const float* enc_img  = (const float*)d_in[0];
    const float* seq      = (const float*)d_in[1];
    const int*   starts   = (const int*)d_in[3];
    const int*   ends     = (const int*)d_in[4];
    const float* W_align  = (const float*)d_in[5];
    const float* b_align  = (const float*)d_in[6];
    const float* Wq       = (const float*)d_in[7];
    const float* Wk       = (const float*)d_in[8];
    const float* Wv       = (const float*)d_in[9];
    const float* Wfc      = (const float*)d_in[10];
    const float* ln_g     = (const float*)d_in[11];
    const float* ln_b     = (const float*)d_in[12];
    const float* W_a1     = (const float*)d_in[13];
    const float* b_a1     = (const float*)d_in[14];
    const float* W_a2     = (const float*)d_in[15];
    const float* b_a2     = (const float*)d_in[16];
    const float* W_un     = (const float*)d_in[17];
    const float* b_un     = (const float*)d_in[18];
    const float* W_dense  = (const float*)d_in[19];
    const float* b_dense  = (const float*)d_in[20];
    const float* W_cls    = (const float*)d_in[21];
    const float* b_cls    = (const float*)d_in[22];
    float* out = (float*)d_out;

    float *res, *kvproj, *ktil, *vtil, *span, *P, *ctx, *cat, *h1, *f2, *pool, *tb;
    float *encr, *wal, *wkv, *wqt, *wfc, *wa1, *wa2, *wd;
    cudaGetSymbolAddress((void**)&res,    g_res);
    cudaGetSymbolAddress((void**)&kvproj, g_kvproj);
    cudaGetSymbolAddress((void**)&ktil,   g_ktil);
    cudaGetSymbolAddress((void**)&vtil,   g_vtil);
    cudaGetSymbolAddress((void**)&span,   g_span);
    cudaGetSymbolAddress((void**)&P,      g_P);
    cudaGetSymbolAddress((void**)&ctx,    g_ctx);
    cudaGetSymbolAddress((void**)&cat,    g_cat);
    cudaGetSymbolAddress((void**)&h1,     g_h1);
    cudaGetSymbolAddress((void**)&f2,     g_f2);
    cudaGetSymbolAddress((void**)&pool,   g_pool);
    cudaGetSymbolAddress((void**)&tb,     g_t);
    cudaGetSymbolAddress((void**)&encr,   g_encr);
    cudaGetSymbolAddress((void**)&wal,    g_Wal);
    cudaGetSymbolAddress((void**)&wkv,    g_Wkv);
    cudaGetSymbolAddress((void**)&wqt,    g_WqT);
    cudaGetSymbolAddress((void**)&wfc,    g_Wfc);
    cudaGetSymbolAddress((void**)&wa1,    g_Wa1);
    cudaGetSymbolAddress((void**)&wa2,    g_Wa2);
    cudaGetSymbolAddress((void**)&wd,     g_Wd);

    // allow 62 KB dynamic smem on the GEMM instantiations
    cudaFuncSetAttribute(gemmtf<0, 1>, cudaFuncAttributeMaxDynamicSharedMemorySize, GEMM_SMEM);
    cudaFuncSetAttribute(gemmtf<0, 0>, cudaFuncAttributeMaxDynamicSharedMemorySize, GEMM_SMEM);
    cudaFuncSetAttribute(gemmtf<1, 1>, cudaFuncAttributeMaxDynamicSharedMemorySize, GEMM_SMEM);
    cudaFuncSetAttribute(gemmtf<1, 0>, cudaFuncAttributeMaxDynamicSharedMemorySize, GEMM_SMEM);

    // -1) pre-round all GEMM operand matrices (Wk|Wv packed into wkv)
    RJobs jobs;
    int big = 1 << 28;
    jobs.j[0] = { (const float4*)enc_img, (float4*)encr, 16 * 49 * 2048 / 4, big, big };
    jobs.j[1] = { (const float4*)W_align, (float4*)wal,  2048 * 768 / 4,     big, big };
    jobs.j[2] = { (const float4*)Wk,      (float4*)wkv,          768 * 6144 / 4, 1536, 3072 };
    jobs.j[3] = { (const float4*)Wv,      (float4*)wkv + 1536,   768 * 6144 / 4, 1536, 3072 };
    jobs.j[4] = { (const float4*)Wfc,     (float4*)wfc,  6144 * 768 / 4,     big, big };
    jobs.j[5] = { (const float4*)W_a1,    (float4*)wa1,  1536 * 1536 / 4,    big, big };
    jobs.j[6] = { (const float4*)W_a2,    (float4*)wa2,  1536 * 768 / 4,     big, big };
    jobs.j[7] = { (const float4*)W_dense, (float4*)wd,   768 * 768 / 4,      big, big };
    round8<<<dim3(1024, 8), 256>>>(jobs);
    transposeWq<<<dim3(24, 24, 8), dim3(32, 8)>>>(Wq, wqt);

    // 0) res = enc_img @ W_align + b_align        [784,768]  (rounded)
    gemmtf<0, 1><<<dim3(6, 7, 1), 256, GEMM_SMEM>>>(
        encr, wal, b_align, res, SR, 768, 2048, 2048, 768, 768, 0, 0, 0);
    // 1) kvproj = res @ [Wk|Wv]                   [784,12288] (rounded)
    gemmtf<0, 1><<<dim3(96, 7, 1), 256, GEMM_SMEM>>>(
        res, wkv, nullptr, kvproj, SR, 12288, 768, 768, 12288, 12288, 0, 0, 0);
    // 2) ktil_h = kproj_h @ WqT_h (batched)       [8,784,768] (raw)
    gemmtf<0, 0><<<dim3(6, 7, HH), 256, GEMM_SMEM>>>(
        kvproj, wqt, nullptr, ktil, SR, 768, 768, 12288, 768, 768,
        768LL, 768LL * 768LL, (long long)SR * 768);
    // 3) vtil_h = vproj_h @ Wfc_h (batched)       [8,784,768] (raw)
    gemmtf<0, 0><<<dim3(6, 7, HH), 256, GEMM_SMEM>>>(
        kvproj + 6144, wfc, nullptr, vtil, SR, 768, 768, 12288, 768, 768,
        768LL, 768LL * 768LL, (long long)SR * 768);
    // 4) span gather (raw span, rounded cat-left)
    gather_kernel<<<NQ, 192>>>(seq, starts, span, cat);
    // 5) attention logits + softmax -> P (fp32)
    attn_kernel<<<dim3(HH, NM), 256>>>(span, ktil, P);
    // 6) AV + residual -> ctx (fp32)
    av_kernel<<<dim3(3, NM), 256>>>(P, vtil, span, ctx);
    // 7) layernorm -> cat right half (rounded, stride 1536)
    ln_kernel<<<NQ, 256>>>(ctx, ln_g, ln_b, cat + DD, 2 * DD);
    // 8) h1 = tanh(cat @ W_a1 + b_a1)             [3840,1536] (rounded)
    gemmtf<1, 1><<<dim3(12, 30, 1), 256, GEMM_SMEM>>>(
        cat, wa1, b_a1, h1, NQ, 1536, 1536, 1536, 1536, 1536, 0, 0, 0);
    // 9) f2 = h1 @ W_a2 + b_a2                    [3840,768] (raw)
    gemmtf<0, 0><<<dim3(6, 30, 1), 256, GEMM_SMEM>>>(
        h1, wa2, b_a2, f2, NQ, 768, 1536, 1536, 768, 768, 0, 0, 0);
    // 10) score + masked softmax + pooled (rounded) [128,768]
    pool_kernel<<<NM, 256>>>(f2, W_un, b_un, starts, ends, pool);
    // 11) t = tanh(pool @ W_dense + b_dense)      [128,768] (raw)
    gemmtf<1, 0><<<dim3(6, 1, 1), 256, GEMM_SMEM>>>(
        pool, wd, b_dense, tb, NM, 768, 768, 768, 768, 768, 0, 0, 0);
    // 12) logits = t @ W_cls + b_cls              [128,4]
    cls_kernel<<<NM, 128>>>(tb, W_cls, b_cls, out);
}

// round 8
// speedup vs baseline: 3.4399x; 1.3107x over previous
#include <cuda_runtime.h>
#include <cuda_fp16.h>
#include <math.h>
#include <stdint.h>

// Problem constants
#define NB 16
#define LSEQ 128
#define DD 768
#define HH 8
#define JR 30
#define RR 49
#define NM 128       // N*M spans
#define NQ 3840      // NM*JR rows
#define SR 784       // NB*RR rows

// ---------------- scratch ----------------
// fp16 activations (A operands of GEMMs)
__device__ __align__(16) half  g_enc_h [16 * 49 * 2048];
__device__ __align__(16) half  g_res_h [SR * DD];
__device__ __align__(16) half  g_kv_h  [SR * 2 * HH * DD];    // kproj|vproj [784,12288]
__device__ __align__(16) half  g_cat_h [NQ * 2 * DD];
__device__ __align__(16) half  g_h1_h  [NQ * 2 * DD];
__device__ __align__(16) half  g_pool_h[NM * DD];
// fp32 buffers
__device__ __align__(16) float g_til  [2 * HH * SR * DD];     // ktil(8) | vtil(8)
__device__ __align__(16) float g_span [NQ * DD];
__device__ __align__(16) float g_P    [NM * HH * JR * RR];
__device__ __align__(16) float g_ctx  [NQ * DD];
__device__ __align__(16) float g_f2   [NQ * DD];
__device__ __align__(16) float g_t    [NM * DD];
// k-pair-packed half2 weights (B operands): u32 element = (half k_even, half k_odd)
__device__ __align__(16) uint32_t g_Walp [1024 * 768];
__device__ __align__(16) uint32_t g_Wkvp [384 * 12288];
__device__ __align__(16) uint32_t g_WTp  [16 * 384 * 768];    // WqT heads | Wfc heads
__device__ __align__(16) uint32_t g_Wa1p [768 * 1536];
__device__ __align__(16) uint32_t g_Wa2p [768 * 768];
__device__ __align__(16) uint32_t g_Wdp  [384 * 768];

// ---------------- helpers ----------------
__device__ __forceinline__ uint32_t pack2(float a, float b) {
    __half2 h = __floats2half2_rn(a, b);   // x (lo) = a, y (hi) = b
    return *(uint32_t*)&h;
}

__device__ __forceinline__ void mma16(float* c, const uint32_t* a, const uint32_t* b) {
    asm volatile(
        "mma.sync.aligned.m16n8k16.row.col.f32.f16.f16.f32 "
        "{%0,%1,%2,%3},{%4,%5,%6,%7},{%8,%9},{%0,%1,%2,%3};"
        : "+f"(c[0]), "+f"(c[1]), "+f"(c[2]), "+f"(c[3])
        : "r"(a[0]), "r"(a[1]), "r"(a[2]), "r"(a[3]), "r"(b[0]), "r"(b[1]));
}

__device__ __forceinline__ void cpa16(uint32_t saddr, const void* g) {
    asm volatile("cp.async.ca.shared.global [%0], [%1], 16;\n" :: "r"(saddr), "l"(g));
}
__device__ __forceinline__ void cpa_commit() {
    asm volatile("cp.async.commit_group;\n");
}
template<int N>
__device__ __forceinline__ void cpa_wait() {
    asm volatile("cp.async.wait_group %0;\n" :: "n"(N));
}

// ---------------- prep: fp32 -> fp16 conversions ----------------
// enc_img: plain contiguous convert (A operand)
__global__ void conv_half(const float4* __restrict__ src, uint2* __restrict__ dst, int n4) {
    for (int i = blockIdx.x * blockDim.x + threadIdx.x; i < n4; i += gridDim.x * blockDim.x) {
        float4 v = src[i];
        uint2 u;
        u.x = pack2(v.x, v.y);
        u.y = pack2(v.z, v.w);
        dst[i] = u;
    }
}

// B weights: [K,N] fp32 -> [K/2, dstld] u32 packing rows 2k2, 2k2+1 at col n
struct PJob { const float* src; uint32_t* dst; int K2; int N; int srcld; int dstld; int dstoff; };
struct PJobs { PJob j[7]; };

__global__ void packB(PJobs jobs) {
    PJob jb = jobs.j[blockIdx.y];
    int total = jb.K2 * jb.N;
    for (int i = blockIdx.x * blockDim.x + threadIdx.x; i < total;
         i += gridDim.x * blockDim.x) {
        int k2 = i / jb.N, n = i - k2 * jb.N;
        float lo = jb.src[(long long)(2 * k2) * jb.srcld + n];
        float hi = jb.src[(long long)(2 * k2 + 1) * jb.srcld + n];
        jb.dst[(long long)k2 * jb.dstld + jb.dstoff + n] = pack2(lo, hi);
    }
}

// Wq [768(i), 6144] -> packed WqT per head: WTp[h][d2][j] = (Wq[j][h*768+2d2], Wq[j][h*768+2d2+1])
__global__ void transposeWqPack(const float* __restrict__ Wq, uint32_t* __restrict__ WTp) {
    __shared__ float t[32][33];     // t[j_local][d_local]
    int h = blockIdx.z;
    int j0 = blockIdx.y * 32, d0 = blockIdx.x * 32;
    int tx = threadIdx.x, ty = threadIdx.y;   // 32 x 8
    #pragma unroll
    for (int dy = 0; dy < 32; dy += 8)
        t[ty + dy][tx] = Wq[(long long)(j0 + ty + dy) * 6144 + h * 768 + d0 + tx];
    __syncthreads();
    #pragma unroll
    for (int dy2 = 0; dy2 < 16; dy2 += 8) {
        int dd = ty + dy2;                    // local d2 index 0..15
        uint32_t u = pack2(t[tx][2 * dd], t[tx][2 * dd + 1]);
        WTp[(long long)h * 384 * 768 + (long long)(d0 / 2 + dd) * 768 + j0 + tx] = u;
    }
}

// ---------------- FP16 tensor-core GEMM, cp.async multistage -----------------
// BK=32 halves per stage (2 x k16 sub-blocks), NS=4 stages, ONE barrier/stage.
// 128x128 CTA tile, 256 threads (8 warps of 64x32). N%128==0, K%32==0,
// M bounds-checked. A: half [M,K] row-major. B: k-pair-packed u32 [K/2, N].
// OUTH: write half output, else float. Dynamic smem: 83968 B.
#define STAGE_U32 5248              // 2*128*12 (A subs) + 2*8*136 (B subs)
#define GEMM_SMEM (4 * STAGE_U32 * 4)

template<int ACT, int OUTH>
__global__ __launch_bounds__(256, 2)
void gemmfp16(const half* __restrict__ A, const uint32_t* __restrict__ B,
              const float* __restrict__ bias, void* __restrict__ Cv,
              int M, int N, int K, int lda, int ldb, int ldc,
              long long aBS, long long bBS, long long cBS)
{
    constexpr int NS = 4;
    extern __shared__ uint32_t sm[];

    A += (long long)blockIdx.z * aBS;
    B += (long long)blockIdx.z * bBS;

    const int tid = threadIdx.x;
    const int warp = tid >> 5, lane = tid & 31;
    const int g = lane >> 2, tig = lane & 3;
    const int wm = warp & 1, wn = warp >> 1;     // 2x4 warps: 64x32 each
    const int bm = blockIdx.y * 128, bn = blockIdx.x * 128;

    // loader coords
    const int la_row = tid >> 1, la_half = tid & 1;   // A: row, 16B (8-half) slice
    const int lb_k = tid >> 5, lb_n4 = tid & 31;      // B: u32-row, 16B (4-u32) col group

    const half* aP = A + (long long)min(bm + la_row, M - 1) * lda + la_half * 8;
    const uint32_t* bP = B + (long long)lb_k * ldb + bn + lb_n4 * 4;

    const uint32_t smbase = (uint32_t)__cvta_generic_to_shared(sm);
    const uint32_t a_off = (la_row * 12 + la_half * 4) * 4;
    const uint32_t b_off = (lb_k * 136 + lb_n4 * 4) * 4;

    float acc[4][4][4];
    #pragma unroll
    for (int mt = 0; mt < 4; mt++)
        #pragma unroll
        for (int nt = 0; nt < 4; nt++)
            #pragma unroll
            for (int i = 0; i < 4; i++) acc[mt][nt][i] = 0.f;

    const int Kt = K >> 5;          // k32 per stage

    auto load_stage = [&](int buf, int kt) {
        uint32_t sb = smbase + buf * (STAGE_U32 * 4);
        const half* ak = aP + kt * 32;
        const uint32_t* bk = bP + (long long)kt * 16 * ldb;
        cpa16(sb + a_off,         ak);                            // A sub0 (k 0..15)
        cpa16(sb + 6144 + a_off,  ak + 16);                       // A sub1 (k 16..31)
        cpa16(sb + 12288 + b_off, bk);                            // B sub0 (k2 0..7)
        cpa16(sb + 16640 + b_off, bk + (long long)8 * ldb);       // B sub1 (k2 8..15)
    };

    load_stage(0, 0); cpa_commit();
    load_stage(1, 1); cpa_commit();
    load_stage(2, 2); cpa_commit();

    for (int kt = 0; kt < Kt; kt++) {
        cpa_wait<NS - 2>();
        __syncthreads();     // stage kt visible; buffer (kt-1)%NS free

        const int buf = kt & 3;
        const uint32_t* As = sm + buf * STAGE_U32;

        #pragma unroll
        for (int s2 = 0; s2 < 2; s2++) {
            const uint32_t* Ap = As + s2 * 1536;
            const uint32_t* Bp = As + 3072 + s2 * 1088;
            uint32_t af[4][4], bf[4][2];
            #pragma unroll
            for (int mt = 0; mt < 4; mt++) {
                const uint32_t* p = Ap + (wm * 64 + mt * 16 + g) * 12;
                af[mt][0] = p[tig];            // (row g,   k-pair lo)
                af[mt][1] = p[96 + tig];       // (row g+8, k-pair lo)
                af[mt][2] = p[tig + 4];        // (row g,   k-pair hi)
                af[mt][3] = p[96 + tig + 4];   // (row g+8, k-pair hi)
            }
            #pragma unroll
            for (int nt = 0; nt < 4; nt++) {
                int c = wn * 32 + nt * 8 + g;
                bf[nt][0] = Bp[tig * 136 + c];
                bf[nt][1] = Bp[(tig + 4) * 136 + c];
            }
            #pragma unroll
            for (int mt = 0; mt < 4; mt++)
                #pragma unroll
                for (int nt = 0; nt < 4; nt++)
                    mma16(acc[mt][nt], af[mt], bf[nt]);
        }

        int nk = kt + NS - 1;
        if (nk < Kt) load_stage(nk & 3, nk);
        cpa_commit();
    }

    // epilogue
    #pragma unroll
    for (int mt = 0; mt < 4; mt++) {
        int r0 = bm + wm * 64 + mt * 16 + g;
        int r1 = r0 + 8;
        #pragma unroll
        for (int nt = 0; nt < 4; nt++) {
            int c = bn + wn * 32 + nt * 8 + 2 * tig;
            float b0 = bias ? bias[c] : 0.f;
            float b1 = bias ? bias[c + 1] : 0.f;
            float v0 = acc[mt][nt][0] + b0, v1 = acc[mt][nt][1] + b1;
            float v2 = acc[mt][nt][2] + b0, v3 = acc[mt][nt][3] + b1;
            if (ACT == 1) { v0 = tanhf(v0); v1 = tanhf(v1); v2 = tanhf(v2); v3 = tanhf(v3); }
            if (OUTH) {
                half* C = (half*)Cv + (long long)blockIdx.z * cBS;
                if (r0 < M) *(uint32_t*)(C + (long long)r0 * ldc + c) = pack2(v0, v1);
                if (r1 < M) *(uint32_t*)(C + (long long)r1 * ldc + c) = pack2(v2, v3);
            } else {
                float* C = (float*)Cv + (long long)blockIdx.z * cBS;
                if (r0 < M) *(float2*)(C + (long long)r0 * ldc + c) = make_float2(v0, v1);
                if (r1 < M) *(float2*)(C + (long long)r1 * ldc + c) = make_float2(v2, v3);
            }
        }
    }
}

// ---------------- span gather (fp32 -> span, fp16 -> cat left) -------------
__global__ void gather_kernel(const float* __restrict__ seq,
                              const int* __restrict__ starts,
                              float* __restrict__ out, half* __restrict__ cat)
{
    int sq = blockIdx.x;
    int s = sq / JR, q = sq - s * JR;
    int gstart = starts[s] + (s >> 3) * LSEQ;
    int idx = min(gstart + q, NB * LSEQ - 1);
    const float4* src = (const float4*)(seq + (long long)idx * DD);
    float4* dst = (float4*)(out + (long long)sq * DD);
    uint2* dst2 = (uint2*)(cat + (long long)sq * 2 * DD);
    for (int i = threadIdx.x; i < DD / 4; i += blockDim.x) {
        float4 v = src[i];
        dst[i] = v;
        uint2 u;
        u.x = pack2(v.x, v.y);
        u.y = pack2(v.z, v.w);
        dst2[i] = u;
    }
}

// ---------------- attention logits + softmax ------------------------------
__global__ __launch_bounds__(256)
void attn_kernel(const float* __restrict__ span, const float* __restrict__ ktil,
                 float* __restrict__ P)
{
    int h = blockIdx.x;
    int s = blockIdx.y;
    int ns = s >> 3;
    __shared__ float sa[JR][33];
    __shared__ float sb[RR][33];
    __shared__ float sl[JR * RR];

    int tid = threadIdx.x;
    float acc[6] = {0.f, 0.f, 0.f, 0.f, 0.f, 0.f};
    int qi[6], ri[6];
    #pragma unroll
    for (int i = 0; i < 6; i++) {
        int p = tid + 256 * i;
        qi[i] = p / RR;
        ri[i] = p - qi[i] * RR;
    }

    const float* sp = span + (long long)s * JR * DD;
    const float* kp = ktil + (long long)(h * SR + ns * RR) * DD;

    for (int k0 = 0; k0 < DD; k0 += 32) {
        if (tid < 240) {
            int row = tid >> 3, c4 = (tid & 7) << 2;
            float4 v = *(const float4*)(sp + (long long)row * DD + k0 + c4);
            sa[row][c4] = v.x; sa[row][c4 + 1] = v.y;
            sa[row][c4 + 2] = v.z; sa[row][c4 + 3] = v.w;
        }
        for (int i = tid; i < RR * 8; i += 256) {
            int row = i >> 3, c4 = (i & 7) << 2;
            float4 v = *(const float4*)(kp + (long long)row * DD + k0 + c4);
            sb[row][c4] = v.x; sb[row][c4 + 1] = v.y;
            sb[row][c4 + 2] = v.z; sb[row][c4 + 3] = v.w;
        }
        __syncthreads();
        #pragma unroll
        for (int i = 0; i < 6; i++) {
            if (tid + 256 * i < JR * RR) {
                float a = 0.f;
                #pragma unroll
                for (int kk = 0; kk < 32; kk++)
                    a += sa[qi[i]][kk] * sb[ri[i]][kk];
                acc[i] += a;
            }
        }
        __syncthreads();
    }

    const float scale = rsqrtf((float)DD);
    #pragma unroll
    for (int i = 0; i < 6; i++) {
        int p = tid + 256 * i;
        if (p < JR * RR) sl[p] = acc[i] * scale;
    }
    __syncthreads();

    int warp = tid >> 5, lane = tid & 31;
    for (int q = warp; q < JR; q += 8) {
        float v0 = sl[q * RR + lane];
        float v1 = (lane + 32 < RR) ? sl[q * RR + lane + 32] : -3.0e38f;
        float m = fmaxf(v0, v1);
        #pragma unroll
        for (int o = 16; o; o >>= 1) m = fmaxf(m, __shfl_xor_sync(0xffffffffu, m, o));
        float e0 = expf(v0 - m);
        float e1 = (lane + 32 < RR) ? expf(v1 - m) : 0.f;
        float sum = e0 + e1;
        #pragma unroll
        for (int o = 16; o; o >>= 1) sum += __shfl_xor_sync(0xffffffffu, sum, o);
        float inv = 1.f / sum;
        float* Pr = P + (long long)((s * HH + h) * JR + q) * RR;
        Pr[lane] = e0 * inv;
        if (lane + 32 < RR) Pr[lane + 32] = e1 * inv;
    }
}

// ---------------- attention-value + residual ------------------------------
__global__ __launch_bounds__(256)
void av_kernel(const float* __restrict__ P, const float* __restrict__ vtil,
               const float* __restrict__ span, float* __restrict__ ctx)
{
    int s = blockIdx.y;
    int o = blockIdx.x * 256 + threadIdx.x;
    int ns = s >> 3;
    __shared__ float Ps[HH * JR * RR];
    for (int i = threadIdx.x; i < HH * JR * RR; i += 256)
        Ps[i] = P[(long long)s * HH * JR * RR + i];
    __syncthreads();

    float acc[JR];
    #pragma unroll
    for (int q = 0; q < JR; q++) acc[q] = 0.f;

    for (int h = 0; h < HH; h++) {
        const float* vp = vtil + (long long)(h * SR + ns * RR) * DD + o;
        const float* pp = Ps + h * JR * RR;
        for (int r = 0; r < RR; r++) {
            float v = vp[(long long)r * DD];
            #pragma unroll
            for (int q = 0; q < JR; q++)
                acc[q] += pp[q * RR + r] * v;
        }
    }
    const float* sp = span + (long long)s * JR * DD + o;
    float* cp = ctx + (long long)s * JR * DD + o;
    #pragma unroll
    for (int q = 0; q < JR; q++)
        cp[(long long)q * DD] = acc[q] + sp[(long long)q * DD];
}

// ---------------- layernorm (fp16 strided output into cat right) -----------
__global__ __launch_bounds__(256)
void ln_kernel(const float* __restrict__ X, const float* __restrict__ g,
               const float* __restrict__ b, half* __restrict__ Y, int ostride)
{
    int r = blockIdx.x;
    int t = threadIdx.x;
    const float* x = X + (long long)r * DD;
    float v0 = x[t], v1 = x[t + 256], v2 = x[t + 512];
    __shared__ float red[8];

    float s = v0 + v1 + v2;
    #pragma unroll
    for (int o = 16; o; o >>= 1) s += __shfl_xor_sync(0xffffffffu, s, o);
    if ((t & 31) == 0) red[t >> 5] = s;
    __syncthreads();
    if (t == 0) { float z = 0.f; for (int i = 0; i < 8; i++) z += red[i]; red[0] = z; }
    __syncthreads();
    float mu = red[0] * (1.0f / DD);
    __syncthreads();

    float d0 = v0 - mu, d1 = v1 - mu, d2 = v2 - mu;
    float ss = d0 * d0 + d1 * d1 + d2 * d2;
    #pragma unroll
    for (int o = 16; o; o >>= 1) ss += __shfl_xor_sync(0xffffffffu, ss, o);
    if ((t & 31) == 0) red[t >> 5] = ss;
    __syncthreads();
    if (t == 0) { float z = 0.f; for (int i = 0; i < 8; i++) z += red[i]; red[0] = z; }
    __syncthreads();
    float inv = rsqrtf(red[0] * (1.0f / DD) + 1e-5f);

    half* y = Y + (long long)r * ostride;
    y[t]       = __float2half_rn(d0 * inv * g[t]       + b[t]);
    y[t + 256] = __float2half_rn(d1 * inv * g[t + 256] + b[t + 256]);
    y[t + 512] = __float2half_rn(d2 * inv * g[t + 512] + b[t + 512]);
}

// ---------------- unary score + masked softmax + pooling --------------------
__global__ __launch_bounds__(256)
void pool_kernel(const float* __restrict__ F2, const float* __restrict__ W_un,
                 const float* __restrict__ b_un, const int* __restrict__ starts,
                 const int* __restrict__ ends, half* __restrict__ pooled)
{
    int s = blockIdx.x;
    __shared__ float sc[JR];
    __shared__ float pr[32];
    int tid = threadIdx.x, warp = tid >> 5, lane = tid & 31;

    for (int q = warp; q < JR; q += 8) {
        const float* row = F2 + (long long)(s * JR + q) * DD;
        float acc = 0.f;
        for (int k = lane; k < DD; k += 32) acc += row[k] * W_un[k];
        #pragma unroll
        for (int o = 16; o; o >>= 1) acc += __shfl_xor_sync(0xffffffffu, acc, o);
        if (lane == 0) sc[q] = acc + b_un[0];
    }
    __syncthreads();

    if (tid < 32) {
        int width = ends[s] - starts[s] + 1;
        float v = -3.0e38f;
        if (tid < JR) {
            v = sc[tid];
            if (tid >= width) v += -10000.0f;
        }
        float m = v;
        #pragma unroll
        for (int o = 16; o; o >>= 1) m = fmaxf(m, __shfl_xor_sync(0xffffffffu, m, o));
        float e = (tid < JR) ? expf(v - m) : 0.f;
        float sum = e;
        #pragma unroll
        for (int o = 16; o; o >>= 1) sum += __shfl_xor_sync(0xffffffffu, sum, o);
        pr[tid] = (tid < JR) ? e / sum : 0.f;
    }
    __syncthreads();

    for (int o = tid; o < DD; o += 256) {
        float acc = 0.f;
        #pragma unroll
        for (int q = 0; q < JR; q++)
            acc += pr[q] * F2[(long long)(s * JR + q) * DD + o];
        pooled[(long long)s * DD + o] = __float2half_rn(acc);
    }
}

// ---------------- classifier ------------------------------------------------
__global__ void cls_kernel(const float* __restrict__ T, const float* __restrict__ Wc,
                           const float* __restrict__ bc, float* __restrict__ out)
{
    int s = blockIdx.x;
    int c = threadIdx.x >> 5, lane = threadIdx.x & 31;
    const float* t = T + (long long)s * DD;
    float acc = 0.f;
    for (int k = lane; k < DD; k += 32) acc += t[k] * Wc[k * 4 + c];
    #pragma unroll
    for (int o = 16; o; o >>= 1) acc += __shfl_xor_sync(0xffffffffu, acc, o);
    if (lane == 0) out[s * 4 + c] = acc + bc[c];
}

// ---------------- launcher --------------------------------------------------
extern "C" void kernel_launch(void* const* d_in, const int* in_sizes, int n_in,
                              void* d_out, int out_size)
{
    const float* enc_img  = (const float*)d_in[0];
    const float* seq      = (const float*)d_in[1];
    const int*   starts   = (const int*)d_in[3];
    const int*   ends     = (const int*)d_in[4];
    const float* W_align  = (const float*)d_in[5];
    const float* b_align  = (const float*)d_in[6];
    const float* Wq       = (const float*)d_in[7];
    const float* Wk       = (const float*)d_in[8];
    const float* Wv       = (const float*)d_in[9];
    const float* Wfc      = (const float*)d_in[10];
    const float* ln_g     = (const float*)d_in[11];
    const float* ln_b     = (const float*)d_in[12];
    const float* W_a1     = (const float*)d_in[13];
    const float* b_a1     = (const float*)d_in[14];
    const float* W_a2     = (const float*)d_in[15];
    const float* b_a2     = (const float*)d_in[16];
    const float* W_un     = (const float*)d_in[17];
    const float* b_un     = (const float*)d_in[18];
    const float* W_dense  = (const float*)d_in[19];
    const float* b_dense  = (const float*)d_in[20];
    const float* W_cls    = (const float*)d_in[21];
    const float* b_cls    = (const float*)d_in[22];
    float* out = (float*)d_out;

    half *ench, *resh, *kvh, *cath, *h1h, *poolh;
    float *til, *span, *P, *ctx, *f2, *tb;
    uint32_t *walp, *wkvp, *wtp, *wa1p, *wa2p, *wdp;
    cudaGetSymbolAddress((void**)&ench,  g_enc_h);
    cudaGetSymbolAddress((void**)&resh,  g_res_h);
    cudaGetSymbolAddress((void**)&kvh,   g_kv_h);
    cudaGetSymbolAddress((void**)&cath,  g_cat_h);
    cudaGetSymbolAddress((void**)&h1h,   g_h1_h);
    cudaGetSymbolAddress((void**)&poolh, g_pool_h);
    cudaGetSymbolAddress((void**)&til,   g_til);
    cudaGetSymbolAddress((void**)&span,  g_span);
    cudaGetSymbolAddress((void**)&P,     g_P);
    cudaGetSymbolAddress((void**)&ctx,   g_ctx);
    cudaGetSymbolAddress((void**)&f2,    g_f2);
    cudaGetSymbolAddress((void**)&tb,    g_t);
    cudaGetSymbolAddress((void**)&walp,  g_Walp);
    cudaGetSymbolAddress((void**)&wkvp,  g_Wkvp);
    cudaGetSymbolAddress((void**)&wtp,   g_WTp);
    cudaGetSymbolAddress((void**)&wa1p,  g_Wa1p);
    cudaGetSymbolAddress((void**)&wa2p,  g_Wa2p);
    cudaGetSymbolAddress((void**)&wdp,   g_Wdp);

    // allow 84 KB dynamic smem on the GEMM instantiations
    cudaFuncSetAttribute(gemmfp16<0, 0>, cudaFuncAttributeMaxDynamicSharedMemorySize, GEMM_SMEM);
    cudaFuncSetAttribute(gemmfp16<0, 1>, cudaFuncAttributeMaxDynamicSharedMemorySize, GEMM_SMEM);
    cudaFuncSetAttribute(gemmfp16<1, 0>, cudaFuncAttributeMaxDynamicSharedMemorySize, GEMM_SMEM);
    cudaFuncSetAttribute(gemmfp16<1, 1>, cudaFuncAttributeMaxDynamicSharedMemorySize, GEMM_SMEM);

    // -1) prep: convert enc_img to half; pack all B weights (k-pair half2)
    conv_half<<<1024, 256>>>((const float4*)enc_img, (uint2*)ench, 16 * 49 * 2048 / 4);
    PJobs pj;
    pj.j[0] = { W_align, walp,              1024, 768,  768,  768,   0    };
    pj.j[1] = { Wk,      wkvp,              384,  6144, 6144, 12288, 0    };
    pj.j[2] = { Wv,      wkvp,              384,  6144, 6144, 12288, 6144 };
    pj.j[3] = { Wfc,     wtp + 8 * 384 * 768, 3072, 768, 768, 768,   0    };
    pj.j[4] = { W_a1,    wa1p,              768,  1536, 1536, 1536,  0    };
    pj.j[5] = { W_a2,    wa2p,              768,  768,  768,  768,   0    };
    pj.j[6] = { W_dense, wdp,               384,  768,  768,  768,   0    };
    packB<<<dim3(512, 7), 256>>>(pj);
    transposeWqPack<<<dim3(24, 24, 8), dim3(32, 8)>>>(Wq, wtp);

    // 0) res = enc_img @ W_align + b_align        [784,768]  half out
    gemmfp16<0, 1><<<dim3(6, 7, 1), 256, GEMM_SMEM>>>(
        ench, walp, b_align, resh, SR, 768, 2048, 2048, 768, 768, 0, 0, 0);
    // 1) kvproj = res @ [Wk|Wv]                   [784,12288] half out
    gemmfp16<0, 1><<<dim3(96, 7, 1), 256, GEMM_SMEM>>>(
        resh, wkvp, nullptr, kvh, SR, 12288, 768, 768, 12288, 12288, 0, 0, 0);
    // 2) til: z<8 -> ktil_h = kproj_h @ WqT_h; z>=8 -> vtil_h = vproj_h @ Wfc_h
    //    (A col offset z*768 works because vproj starts at col 8*768)  float out
    gemmfp16<0, 0><<<dim3(6, 7, 16), 256, GEMM_SMEM>>>(
        kvh, wtp, nullptr, til, SR, 768, 768, 12288, 768, 768,
        768LL, 384LL * 768LL, (long long)SR * 768);
    // 3) span gather (fp32 span, fp16 cat-left)
    gather_kernel<<<NQ, 192>>>(seq, starts, span, cath);
    // 4) attention logits + softmax -> P (fp32)
    attn_kernel<<<dim3(HH, NM), 256>>>(span, til, P);
    // 5) AV + residual -> ctx (fp32); vtil = til + 8*SR*768
    av_kernel<<<dim3(3, NM), 256>>>(P, til + 8LL * SR * DD, span, ctx);
    // 6) layernorm -> cat right half (fp16, stride 1536)
    ln_kernel<<<NQ, 256>>>(ctx, ln_g, ln_b, cath + DD, 2 * DD);
    // 7) h1 = tanh(cat @ W_a1 + b_a1)             [3840,1536] half out
    gemmfp16<1, 1><<<dim3(12, 30, 1), 256, GEMM_SMEM>>>(
        cath, wa1p, b_a1, h1h, NQ, 1536, 1536, 1536, 1536, 1536, 0, 0, 0);
    // 8) f2 = h1 @ W_a2 + b_a2                    [3840,768] float out
    gemmfp16<0, 0><<<dim3(6, 30, 1), 256, GEMM_SMEM>>>(
        h1h, wa2p, b_a2, f2, NQ, 768, 1536, 1536, 768, 768, 0, 0, 0);
    // 9) score + masked softmax + pooled (fp16)   [128,768]
    pool_kernel<<<NM, 256>>>(f2, W_un, b_un, starts, ends, poolh);
    // 10) t = tanh(pool @ W_dense + b_dense)      [128,768] float out
    gemmfp16<1, 0><<<dim3(6, 1, 1), 256, GEMM_SMEM>>>(
        poolh, wdp, b_dense, tb, NM, 768, 768, 768, 768, 768, 0, 0, 0);
    // 11) logits = t @ W_cls + b_cls              [128,4]
    cls_kernel<<<NM, 128>>>(tb, W_cls, b_cls, out);
}

// round 10
// speedup vs baseline: 6.9236x; 2.0127x over previous
#include <cuda_runtime.h>
#include <cuda_fp16.h>
#include <math.h>
#include <stdint.h>

// Problem constants
#define NB 16
#define LSEQ 128
#define DD 768
#define HH 8
#define JR 30
#define RR 49
#define NM 128       // N*M spans
#define NQ 3840      // NM*JR rows
#define SR 784       // NB*RR rows

// ---------------- scratch ----------------
__device__ __align__(16) half  g_enc_h [16 * 49 * 2048];
__device__ __align__(16) half  g_res_h [SR * DD];
__device__ __align__(16) half  g_kv_h  [SR * 2 * HH * DD];    // kproj|vproj [784,12288]
__device__ __align__(16) half  g_til_h [16 * SR * DD];        // ktil heads 0..7 | vtil heads 8..15
__device__ __align__(16) half  g_cat_h [NQ * 2 * DD];
__device__ __align__(16) half  g_h1_h  [NQ * 2 * DD];
__device__ __align__(16) half  g_pool_h[NM * DD];
__device__ __align__(16) uint32_t g_vtilP[16 * 224 * DD];     // [ns][kpair 224][d] packed pairs
// fp32 buffers
__device__ __align__(16) float g_span [NQ * DD];
__device__ __align__(16) float g_ctx  [NQ * DD];              // also reused for res split-K partials
__device__ __align__(16) float g_f2   [NQ * DD];
__device__ __align__(16) float g_t    [NM * DD];
// k-pair-packed half2 weights (B operands)
__device__ __align__(16) uint32_t g_Walp [1024 * 768];
__device__ __align__(16) uint32_t g_Wkvp [384 * 12288];
__device__ __align__(16) uint32_t g_WTp  [16 * 384 * 768];    // WqT heads | Wfc heads
__device__ __align__(16) uint32_t g_Wa1p [768 * 1536];
__device__ __align__(16) uint32_t g_Wa2p [768 * 768];
__device__ __align__(16) uint32_t g_Wdp  [384 * 768];

// ---------------- helpers ----------------
__device__ __forceinline__ uint32_t pack2(float a, float b) {
    __half2 h = __floats2half2_rn(a, b);
    return *(uint32_t*)&h;
}

__device__ __forceinline__ void mma16(float* c, const uint32_t* a, const uint32_t* b) {
    asm volatile(
        "mma.sync.aligned.m16n8k16.row.col.f32.f16.f16.f32 "
        "{%0,%1,%2,%3},{%4,%5,%6,%7},{%8,%9},{%0,%1,%2,%3};"
        : "+f"(c[0]), "+f"(c[1]), "+f"(c[2]), "+f"(c[3])
        : "r"(a[0]), "r"(a[1]), "r"(a[2]), "r"(a[3]), "r"(b[0]), "r"(b[1]));
}

__device__ __forceinline__ void cpa16(uint32_t saddr, const void* g) {
    asm volatile("cp.async.ca.shared.global [%0], [%1], 16;\n" :: "r"(saddr), "l"(g));
}
__device__ __forceinline__ void cpa_commit() {
    asm volatile("cp.async.commit_group;\n");
}
template<int N>
__device__ __forceinline__ void cpa_wait() {
    asm volatile("cp.async.wait_group %0;\n" :: "n"(N));
}

// ---------------- prep kernels ----------------
__global__ void conv_half(const float4* __restrict__ src, uint2* __restrict__ dst, int n4) {
    for (int i = blockIdx.x * blockDim.x + threadIdx.x; i < n4; i += gridDim.x * blockDim.x) {
        float4 v = src[i];
        uint2 u;
        u.x = pack2(v.x, v.y);
        u.y = pack2(v.z, v.w);
        dst[i] = u;
    }
}

struct PJob { const float* src; uint32_t* dst; int K2; int N; int srcld; int dstld; int dstoff; };
struct PJobs { PJob j[7]; };

__global__ void packB(PJobs jobs) {
    PJob jb = jobs.j[blockIdx.y];
    int total = jb.K2 * jb.N;
    for (int i = blockIdx.x * blockDim.x + threadIdx.x; i < total;
         i += gridDim.x * blockDim.x) {
        int k2 = i / jb.N, n = i - k2 * jb.N;
        float lo = jb.src[(long long)(2 * k2) * jb.srcld + n];
        float hi = jb.src[(long long)(2 * k2 + 1) * jb.srcld + n];
        jb.dst[(long long)k2 * jb.dstld + jb.dstoff + n] = pack2(lo, hi);
    }
}

__global__ void transposeWqPack(const float* __restrict__ Wq, uint32_t* __restrict__ WTp) {
    __shared__ float t[32][33];
    int h = blockIdx.z;
    int j0 = blockIdx.y * 32, d0 = blockIdx.x * 32;
    int tx = threadIdx.x, ty = threadIdx.y;   // 32 x 8
    #pragma unroll
    for (int dy = 0; dy < 32; dy += 8)
        t[ty + dy][tx] = Wq[(long long)(j0 + ty + dy) * 6144 + h * 768 + d0 + tx];
    __syncthreads();
    #pragma unroll
    for (int dy2 = 0; dy2 < 16; dy2 += 8) {
        int dd = ty + dy2;
        uint32_t u = pack2(t[tx][2 * dd], t[tx][2 * dd + 1]);
        WTp[(long long)h * 384 * 768 + (long long)(d0 / 2 + dd) * 768 + j0 + tx] = u;
    }
}

// vtil (fp16, heads 8..15 of til) -> k-pair packed [ns][224][768] with zero pad r>=49
__global__ void vtilP_prep(const half* __restrict__ til, uint32_t* __restrict__ vp) {
    int total = 16 * 224 * DD;
    for (int i = blockIdx.x * blockDim.x + threadIdx.x; i < total;
         i += gridDim.x * blockDim.x) {
        int d = i % DD;
        int t = i / DD;
        int p = t % 224, ns = t / 224;
        int h = p / 28, rp = p - h * 28;
        int r0 = 2 * rp, r1 = 2 * rp + 1;
        const half* base = til + ((long long)(8 + h) * SR + ns * RR) * DD + d;
        half lo = (r0 < RR) ? base[(long long)r0 * DD] : __float2half(0.f);
        half hi = (r1 < RR) ? base[(long long)r1 * DD] : __float2half(0.f);
        __half2 u = __halves2half2(lo, hi);
        vp[i] = *(uint32_t*)&u;
    }
}

// res split-K combine: resh = half(p0 + p1 + bias)
__global__ void resc_kernel(const float* __restrict__ p0, const float* __restrict__ p1,
                            const float* __restrict__ bias, half* __restrict__ out) {
    int i = blockIdx.x * blockDim.x + threadIdx.x;
    if (i < SR * DD) out[i] = __float2half_rn(p0[i] + p1[i] + bias[i % DD]);
}

// ---------------- FP16 tensor-core GEMM, cp.async multistage -----------------
#define STAGE_U32 5248
#define GEMM_SMEM (4 * STAGE_U32 * 4)

template<int ACT, int OUTH>
__global__ __launch_bounds__(256, 2)
void gemmfp16(const half* __restrict__ A, const uint32_t* __restrict__ B,
              const float* __restrict__ bias, void* __restrict__ Cv,
              int M, int N, int K, int lda, int ldb, int ldc,
              long long aBS, long long bBS, long long cBS)
{
    constexpr int NS = 4;
    extern __shared__ uint32_t sm[];

    A += (long long)blockIdx.z * aBS;
    B += (long long)blockIdx.z * bBS;

    const int tid = threadIdx.x;
    const int warp = tid >> 5, lane = tid & 31;
    const int g = lane >> 2, tig = lane & 3;
    const int wm = warp & 1, wn = warp >> 1;
    const int bm = blockIdx.y * 128, bn = blockIdx.x * 128;

    const int la_row = tid >> 1, la_half = tid & 1;
    const int lb_k = tid >> 5, lb_n4 = tid & 31;

    const half* aP = A + (long long)min(bm + la_row, M - 1) * lda + la_half * 8;
    const uint32_t* bP = B + (long long)lb_k * ldb + bn + lb_n4 * 4;

    const uint32_t smbase = (uint32_t)__cvta_generic_to_shared(sm);
    const uint32_t a_off = (la_row * 12 + la_half * 4) * 4;
    const uint32_t b_off = (lb_k * 136 + lb_n4 * 4) * 4;

    float acc[4][4][4];
    #pragma unroll
    for (int mt = 0; mt < 4; mt++)
        #pragma unroll
        for (int nt = 0; nt < 4; nt++)
            #pragma unroll
            for (int i = 0; i < 4; i++) acc[mt][nt][i] = 0.f;

    const int Kt = K >> 5;

    auto load_stage = [&](int buf, int kt) {
        uint32_t sb = smbase + buf * (STAGE_U32 * 4);
        const half* ak = aP + kt * 32;
        const uint32_t* bk = bP + (long long)kt * 16 * ldb;
        cpa16(sb + a_off,         ak);
        cpa16(sb + 6144 + a_off,  ak + 16);
        cpa16(sb + 12288 + b_off, bk);
        cpa16(sb + 16640 + b_off, bk + (long long)8 * ldb);
    };

    load_stage(0, 0); cpa_commit();
    load_stage(1, 1); cpa_commit();
    load_stage(2, 2); cpa_commit();

    for (int kt = 0; kt < Kt; kt++) {
        cpa_wait<NS - 2>();
        __syncthreads();

        const int buf = kt & 3;
        const uint32_t* As = sm + buf * STAGE_U32;

        #pragma unroll
        for (int s2 = 0; s2 < 2; s2++) {
            const uint32_t* Ap = As + s2 * 1536;
            const uint32_t* Bp = As + 3072 + s2 * 1088;
            uint32_t af[4][4], bf[4][2];
            #pragma unroll
            for (int mt = 0; mt < 4; mt++) {
                const uint32_t* p = Ap + (wm * 64 + mt * 16 + g) * 12;
                af[mt][0] = p[tig];
                af[mt][1] = p[96 + tig];
                af[mt][2] = p[tig + 4];
                af[mt][3] = p[96 + tig + 4];
            }
            #pragma unroll
            for (int nt = 0; nt < 4; nt++) {
                int c = wn * 32 + nt * 8 + g;
                bf[nt][0] = Bp[tig * 136 + c];
                bf[nt][1] = Bp[(tig + 4) * 136 + c];
            }
            #pragma unroll
            for (int mt = 0; mt < 4; mt++)
                #pragma unroll
                for (int nt = 0; nt < 4; nt++)
                    mma16(acc[mt][nt], af[mt], bf[nt]);
        }

        int nk = kt + NS - 1;
        if (nk < Kt) load_stage(nk & 3, nk);
        cpa_commit();
    }

    #pragma unroll
    for (int mt = 0; mt < 4; mt++) {
        int r0 = bm + wm * 64 + mt * 16 + g;
        int r1 = r0 + 8;
        #pragma unroll
        for (int nt = 0; nt < 4; nt++) {
            int c = bn + wn * 32 + nt * 8 + 2 * tig;
            float b0 = bias ? bias[c] : 0.f;
            float b1 = bias ? bias[c + 1] : 0.f;
            float v0 = acc[mt][nt][0] + b0, v1 = acc[mt][nt][1] + b1;
            float v2 = acc[mt][nt][2] + b0, v3 = acc[mt][nt][3] + b1;
            if (ACT == 1) { v0 = tanhf(v0); v1 = tanhf(v1); v2 = tanhf(v2); v3 = tanhf(v3); }
            if (OUTH) {
                half* C = (half*)Cv + (long long)blockIdx.z * cBS;
                if (r0 < M) *(uint32_t*)(C + (long long)r0 * ldc + c) = pack2(v0, v1);
                if (r1 < M) *(uint32_t*)(C + (long long)r1 * ldc + c) = pack2(v2, v3);
            } else {
                float* C = (float*)Cv + (long long)blockIdx.z * cBS;
                if (r0 < M) *(float2*)(C + (long long)r0 * ldc + c) = make_float2(v0, v1);
                if (r1 < M) *(float2*)(C + (long long)r1 * ldc + c) = make_float2(v2, v3);
            }
        }
    }
}

// ---------------- fused attention: QK^T + softmax + AV + residual ------------
// One CTA per span s. 8 warps; warp h owns head h in QK phase.
#define SP_OFF  0                    // span fp16: [32][388] u32 (rows 0..29 valid)
#define KT_OFF  12416                // QK: [8][56][36] u32 ; AV: [224][72] u32
#define P16_OFF 28544                // P fp16: [32][228] u32 (k = h*56+r)
#define LG_OFF  35840                // logits fp32: [8][32][58]
#define ATTN_SMEM ((35840 + 14848) * 4)   // 202752 B

__global__ __launch_bounds__(256, 1)
void fused_attn(const half* __restrict__ cat, const half* __restrict__ til,
                const uint32_t* __restrict__ vtilP, const float* __restrict__ span,
                float* __restrict__ ctx)
{
    extern __shared__ uint32_t sm[];
    const int s = blockIdx.x;
    const int ns = s >> 3;
    const int tid = threadIdx.x, warp = tid >> 5, lane = tid & 31;
    const int g = lane >> 2, tig = lane & 3;
    const uint32_t smb = (uint32_t)__cvta_generic_to_shared(sm);

    // preload span tile (30 rows x 768 halves = 96 cpa16 per row)
    for (int i = tid; i < 30 * 96; i += 256) {
        int q = i / 96, j = i - q * 96;
        cpa16(smb + (SP_OFF + q * 388) * 4 + j * 16,
              cat + (long long)(s * JR + q) * 1536 + j * 8);
    }

    // ---- Phase A: logits ----
    float acc[2][7][4];
    #pragma unroll
    for (int mt = 0; mt < 2; mt++)
        #pragma unroll
        for (int nt = 0; nt < 7; nt++)
            #pragma unroll
            for (int i = 0; i < 4; i++) acc[mt][nt][i] = 0.f;

    const int h = warp;
    for (int kc = 0; kc < 12; kc++) {
        // ktil chunk: 8 heads x 49 rows x 64 halves (128 B = 8 cpa16 per row)
        for (int i = tid; i < 8 * RR * 8; i += 256) {
            int hh = i / (RR * 8), rem = i - hh * (RR * 8);
            int r = rem >> 3, j = rem & 7;
            cpa16(smb + (KT_OFF + (hh * 56 + r) * 36) * 4 + j * 16,
                  til + ((long long)hh * SR + ns * RR + r) * DD + kc * 64 + j * 8);
        }
        cpa_commit();
        cpa_wait<0>();
        __syncthreads();

        const uint32_t* sp = sm + SP_OFF;
        const uint32_t* kt = sm + KT_OFF + h * 56 * 36;
        #pragma unroll
        for (int k4 = 0; k4 < 4; k4++) {
            uint32_t af[2][4], bf[7][2];
            #pragma unroll
            for (int mt = 0; mt < 2; mt++) {
                const uint32_t* p = sp + (mt * 16 + g) * 388 + kc * 32 + k4 * 8;
                af[mt][0] = p[tig];
                af[mt][1] = p[8 * 388 + tig];
                af[mt][2] = p[tig + 4];
                af[mt][3] = p[8 * 388 + tig + 4];
            }
            #pragma unroll
            for (int nt = 0; nt < 7; nt++) {
                bf[nt][0] = kt[(nt * 8 + g) * 36 + k4 * 8 + tig];
                bf[nt][1] = kt[(nt * 8 + g) * 36 + k4 * 8 + tig + 4];
            }
            #pragma unroll
            for (int mt = 0; mt < 2; mt++)
                #pragma unroll
                for (int nt = 0; nt < 7; nt++)
                    mma16(acc[mt][nt], af[mt], bf[nt]);
        }
        __syncthreads();
    }

    // store scaled logits to smem
    {
        float* lg = (float*)(sm + LG_OFF) + h * 32 * 58;
        const float scale = rsqrtf((float)DD);
        #pragma unroll
        for (int mt = 0; mt < 2; mt++) {
            int r0 = mt * 16 + g, r1 = r0 + 8;
            #pragma unroll
            for (int nt = 0; nt < 7; nt++) {
                int c = nt * 8 + 2 * tig;
                lg[r0 * 58 + c]     = acc[mt][nt][0] * scale;
                lg[r0 * 58 + c + 1] = acc[mt][nt][1] * scale;
                lg[r1 * 58 + c]     = acc[mt][nt][2] * scale;
                lg[r1 * 58 + c + 1] = acc[mt][nt][3] * scale;
            }
        }
    }
    __syncwarp();

    // ---- softmax (warp h handles its own head) ----
    {
        const float* lg = (const float*)(sm + LG_OFF) + h * 32 * 58;
        uint32_t* P = sm + P16_OFF;
        int rp = lane;
        for (int q = 0; q < JR; q++) {
            float v0 = -3.0e38f, v1 = -3.0e38f;
            if (rp < 25) {
                int r0 = 2 * rp, r1 = 2 * rp + 1;
                if (r0 < RR) v0 = lg[q * 58 + r0];
                if (r1 < RR) v1 = lg[q * 58 + r1];
            }
            float m = fmaxf(v0, v1);
            #pragma unroll
            for (int o = 16; o; o >>= 1) m = fmaxf(m, __shfl_xor_sync(0xffffffffu, m, o));
            float e0 = (v0 > -1.0e38f) ? expf(v0 - m) : 0.f;
            float e1 = (v1 > -1.0e38f) ? expf(v1 - m) : 0.f;
            float sum = e0 + e1;
            #pragma unroll
            for (int o = 16; o; o >>= 1) sum += __shfl_xor_sync(0xffffffffu, sum, o);
            float inv = 1.f / sum;
            if (rp < 28)
                P[q * 228 + h * 28 + rp] = pack2(e0 * inv, e1 * inv);
        }
    }
    __syncthreads();

    // ---- Phase B: ctx = P @ V + span ----
    for (int dn = 0; dn < 12; dn++) {
        for (int i = tid; i < 224 * 16; i += 256) {
            int p = i >> 4, j = i & 15;
            cpa16(smb + (KT_OFF + p * 72) * 4 + j * 16,
                  vtilP + ((long long)ns * 224 + p) * DD + dn * 64 + j * 4);
        }
        cpa_commit();
        cpa_wait<0>();
        __syncthreads();

        float bacc[2][4];
        #pragma unroll
        for (int mt = 0; mt < 2; mt++)
            #pragma unroll
            for (int i = 0; i < 4; i++) bacc[mt][i] = 0.f;

        const uint32_t* Pp = sm + P16_OFF;
        const uint32_t* vp = sm + KT_OFF;
        #pragma unroll
        for (int k28 = 0; k28 < 28; k28++) {
            uint32_t af[2][4], bf[2];
            #pragma unroll
            for (int mt = 0; mt < 2; mt++) {
                const uint32_t* p = Pp + (mt * 16 + g) * 228 + k28 * 8;
                af[mt][0] = p[tig];
                af[mt][1] = p[8 * 228 + tig];
                af[mt][2] = p[tig + 4];
                af[mt][3] = p[8 * 228 + tig + 4];
            }
            bf[0] = vp[(k28 * 8 + tig) * 72 + warp * 8 + g];
            bf[1] = vp[(k28 * 8 + tig + 4) * 72 + warp * 8 + g];
            mma16(bacc[0], af[0], bf);
            mma16(bacc[1], af[1], bf);
        }

        #pragma unroll
        for (int mt = 0; mt < 2; mt++) {
            int r0 = mt * 16 + g, r1 = r0 + 8;
            int c = dn * 64 + warp * 8 + 2 * tig;
            if (r0 < JR) {
                const float2 sp2 = *(const float2*)(span + (long long)(s * JR + r0) * DD + c);
                *(float2*)(ctx + (long long)(s * JR + r0) * DD + c) =
                    make_float2(bacc[mt][0] + sp2.x, bacc[mt][1] + sp2.y);
            }
            if (r1 < JR) {
                const float2 sp2 = *(const float2*)(span + (long long)(s * JR + r1) * DD + c);
                *(float2*)(ctx + (long long)(s * JR + r1) * DD + c) =
                    make_float2(bacc[mt][2] + sp2.x, bacc[mt][3] + sp2.y);
            }
        }
        __syncthreads();
    }
}

// ---------------- span gather (fp32 -> span, fp16 -> cat left) -------------
__global__ void gather_kernel(const float* __restrict__ seq,
                              const int* __restrict__ starts,
                              float* __restrict__ out, half* __restrict__ cat)
{
    int sq = blockIdx.x;
    int s = sq / JR, q = sq - s * JR;
    int gstart = starts[s] + (s >> 3) * LSEQ;
    int idx = min(gstart + q, NB * LSEQ - 1);
    const float4* src = (const float4*)(seq + (long long)idx * DD);
    float4* dst = (float4*)(out + (long long)sq * DD);
    uint2* dst2 = (uint2*)(cat + (long long)sq * 2 * DD);
    for (int i = threadIdx.x; i < DD / 4; i += blockDim.x) {
        float4 v = src[i];
        dst[i] = v;
        uint2 u;
        u.x = pack2(v.x, v.y);
        u.y = pack2(v.z, v.w);
        dst2[i] = u;
    }
}

// ---------------- layernorm (fp16 strided output into cat right) -----------
__global__ __launch_bounds__(256)
void ln_kernel(const float* __restrict__ X, const float* __restrict__ g,
               const float* __restrict__ b, half* __restrict__ Y, int ostride)
{
    int r = blockIdx.x;
    int t = threadIdx.x;
    const float* x = X + (long long)r * DD;
    float v0 = x[t], v1 = x[t + 256], v2 = x[t + 512];
    __shared__ float red[8];

    float s = v0 + v1 + v2;
    #pragma unroll
    for (int o = 16; o; o >>= 1) s += __shfl_xor_sync(0xffffffffu, s, o);
    if ((t & 31) == 0) red[t >> 5] = s;
    __syncthreads();
    if (t == 0) { float z = 0.f; for (int i = 0; i < 8; i++) z += red[i]; red[0] = z; }
    __syncthreads();
    float mu = red[0] * (1.0f / DD);
    __syncthreads();

    float d0 = v0 - mu, d1 = v1 - mu, d2 = v2 - mu;
    float ss = d0 * d0 + d1 * d1 + d2 * d2;
    #pragma unroll
    for (int o = 16; o; o >>= 1) ss += __shfl_xor_sync(0xffffffffu, ss, o);
    if ((t & 31) == 0) red[t >> 5] = ss;
    __syncthreads();
    if (t == 0) { float z = 0.f; for (int i = 0; i < 8; i++) z += red[i]; red[0] = z; }
    __syncthreads();
    float inv = rsqrtf(red[0] * (1.0f / DD) + 1e-5f);

    half* y = Y + (long long)r * ostride;
    y[t]       = __float2half_rn(d0 * inv * g[t]       + b[t]);
    y[t + 256] = __float2half_rn(d1 * inv * g[t + 256] + b[t + 256]);
    y[t + 512] = __float2half_rn(d2 * inv * g[t + 512] + b[t + 512]);
}

// ---------------- unary score + masked softmax + pooling --------------------
__global__ __launch_bounds__(256)
void pool_kernel(const float* __restrict__ F2, const float* __restrict__ W_un,
                 const float* __restrict__ b_un, const int* __restrict__ starts,
                 const int* __restrict__ ends, half* __restrict__ pooled)
{
    int s = blockIdx.x;
    __shared__ float sc[JR];
    __shared__ float pr[32];
    int tid = threadIdx.x, warp = tid >> 5, lane = tid & 31;

    for (int q = warp; q < JR; q += 8) {
        const float* row = F2 + (long long)(s * JR + q) * DD;
        float acc = 0.f;
        for (int k = lane; k < DD; k += 32) acc += row[k] * W_un[k];
        #pragma unroll
        for (int o = 16; o; o >>= 1) acc += __shfl_xor_sync(0xffffffffu, acc, o);
        if (lane == 0) sc[q] = acc + b_un[0];
    }
    __syncthreads();

    if (tid < 32) {
        int width = ends[s] - starts[s] + 1;
        float v = -3.0e38f;
        if (tid < JR) {
            v = sc[tid];
            if (tid >= width) v += -10000.0f;
        }
        float m = v;
        #pragma unroll
        for (int o = 16; o; o >>= 1) m = fmaxf(m, __shfl_xor_sync(0xffffffffu, m, o));
        float e = (tid < JR) ? expf(v - m) : 0.f;
        float sum = e;
        #pragma unroll
        for (int o = 16; o; o >>= 1) sum += __shfl_xor_sync(0xffffffffu, sum, o);
        pr[tid] = (tid < JR) ? e / sum : 0.f;
    }
    __syncthreads();

    for (int o = tid; o < DD; o += 256) {
        float acc = 0.f;
        #pragma unroll
        for (int q = 0; q < JR; q++)
            acc += pr[q] * F2[(long long)(s * JR + q) * DD + o];
        pooled[(long long)s * DD + o] = __float2half_rn(acc);
    }
}

// ---------------- classifier ------------------------------------------------
__global__ void cls_kernel(const float* __restrict__ T, const float* __restrict__ Wc,
                           const float* __restrict__ bc, float* __restrict__ out)
{
    int s = blockIdx.x;
    int c = threadIdx.x >> 5, lane = threadIdx.x & 31;
    const float* t = T + (long long)s * DD;
    float acc = 0.f;
    for (int k = lane; k < DD; k += 32) acc += t[k] * Wc[k * 4 + c];
    #pragma unroll
    for (int o = 16; o; o >>= 1) acc += __shfl_xor_sync(0xffffffffu, acc, o);
    if (lane == 0) out[s * 4 + c] = acc + bc[c];
}

// ---------------- launcher --------------------------------------------------
extern "C" void kernel_launch(void* const* d_in, const int* in_sizes, int n_in,
                              void* d_out, int out_size)
{
    const float* enc_img  = (const float*)d_in[0];
    const float* seq      = (const float*)d_in[1];
    const int*   starts   = (const int*)d_in[3];
    const int*   ends     = (const int*)d_in[4];
    const float* W_align  = (const float*)d_in[5];
    const float* b_align  = (const float*)d_in[6];
    const float* Wq       = (const float*)d_in[7];
    const float* Wk       = (const float*)d_in[8];
    const float* Wv       = (const float*)d_in[9];
    const float* Wfc      = (const float*)d_in[10];
    const float* ln_g     = (const float*)d_in[11];
    const float* ln_b     = (const float*)d_in[12];
    const float* W_a1     = (const float*)d_in[13];
    const float* b_a1     = (const float*)d_in[14];
    const float* W_a2     = (const float*)d_in[15];
    const float* b_a2     = (const float*)d_in[16];
    const float* W_un     = (const float*)d_in[17];
    const float* b_un     = (const float*)d_in[18];
    const float* W_dense  = (const float*)d_in[19];
    const float* b_dense  = (const float*)d_in[20];
    const float* W_cls    = (const float*)d_in[21];
    const float* b_cls    = (const float*)d_in[22];
    float* out = (float*)d_out;

    half *ench, *resh, *kvh, *tilh, *cath, *h1h, *poolh;
    float *span, *ctx, *f2, *tb;
    uint32_t *walp, *wkvp, *wtp, *wa1p, *wa2p, *wdp, *vtp;
    cudaGetSymbolAddress((void**)&ench,  g_enc_h);
    cudaGetSymbolAddress((void**)&resh,  g_res_h);
    cudaGetSymbolAddress((void**)&kvh,   g_kv_h);
    cudaGetSymbolAddress((void**)&tilh,  g_til_h);
    cudaGetSymbolAddress((void**)&cath,  g_cat_h);
    cudaGetSymbolAddress((void**)&h1h,   g_h1_h);
    cudaGetSymbolAddress((void**)&poolh, g_pool_h);
    cudaGetSymbolAddress((void**)&span,  g_span);
    cudaGetSymbolAddress((void**)&ctx,   g_ctx);
    cudaGetSymbolAddress((void**)&f2,    g_f2);
    cudaGetSymbolAddress((void**)&tb,    g_t);
    cudaGetSymbolAddress((void**)&walp,  g_Walp);
    cudaGetSymbolAddress((void**)&wkvp,  g_Wkvp);
    cudaGetSymbolAddress((void**)&wtp,   g_WTp);
    cudaGetSymbolAddress((void**)&wa1p,  g_Wa1p);
    cudaGetSymbolAddress((void**)&wa2p,  g_Wa2p);
    cudaGetSymbolAddress((void**)&wdp,   g_Wdp);
    cudaGetSymbolAddress((void**)&vtp,   g_vtilP);

    cudaFuncSetAttribute(gemmfp16<0, 0>, cudaFuncAttributeMaxDynamicSharedMemorySize, GEMM_SMEM);
    cudaFuncSetAttribute(gemmfp16<0, 1>, cudaFuncAttributeMaxDynamicSharedMemorySize, GEMM_SMEM);
    cudaFuncSetAttribute(gemmfp16<1, 0>, cudaFuncAttributeMaxDynamicSharedMemorySize, GEMM_SMEM);
    cudaFuncSetAttribute(gemmfp16<1, 1>, cudaFuncAttributeMaxDynamicSharedMemorySize, GEMM_SMEM);
    cudaFuncSetAttribute(fused_attn, cudaFuncAttributeMaxDynamicSharedMemorySize, ATTN_SMEM);

    // prep
    conv_half<<<1024, 256>>>((const float4*)enc_img, (uint2*)ench, 16 * 49 * 2048 / 4);
    PJobs pj;
    pj.j[0] = { W_align, walp,                1024, 768,  768,  768,   0    };
    pj.j[1] = { Wk,      wkvp,                384,  6144, 6144, 12288, 0    };
    pj.j[2] = { Wv,      wkvp,                384,  6144, 6144, 12288, 6144 };
    pj.j[3] = { Wfc,     wtp + 8 * 384 * 768, 3072, 768,  768,  768,   0    };
    pj.j[4] = { W_a1,    wa1p,                768,  1536, 1536, 1536,  0    };
    pj.j[5] = { W_a2,    wa2p,                768,  768,  768,  768,   0    };
    pj.j[6] = { W_dense, wdp,                 384,  768,  768,  768,   0    };
    packB<<<dim3(512, 7), 256>>>(pj);
    transposeWqPack<<<dim3(24, 24, 8), dim3(32, 8)>>>(Wq, wtp);

    // 0) res split-K=2: partials into ctx scratch, then combine
    gemmfp16<0, 0><<<dim3(6, 7, 2), 256, GEMM_SMEM>>>(
        ench, walp, nullptr, ctx, SR, 768, 1024, 2048, 768, 768,
        1024LL, 512LL * 768LL, (long long)SR * 768);
    resc_kernel<<<(SR * DD + 255) / 256, 256>>>(ctx, ctx + (long long)SR * DD, b_align, resh);

    // 1) kvproj = res @ [Wk|Wv]     [784,12288] half out
    gemmfp16<0, 1><<<dim3(96, 7, 1), 256, GEMM_SMEM>>>(
        resh, wkvp, nullptr, kvh, SR, 12288, 768, 768, 12288, 12288, 0, 0, 0);
    // 2) til (fp16): z<8 ktil_h = kproj_h @ WqT_h; z>=8 vtil_h = vproj_h @ Wfc_h
    gemmfp16<0, 1><<<dim3(6, 7, 16), 256, GEMM_SMEM>>>(
        kvh, wtp, nullptr, tilh, SR, 768, 768, 12288, 768, 768,
        768LL, 384LL * 768LL, (long long)SR * 768);
    // 3) span gather
    gather_kernel<<<NQ, 192>>>(seq, starts, span, cath);
    // 4) vtil pack for AV
    vtilP_prep<<<2048, 256>>>(tilh, vtp);
    // 5) fused attention -> ctx
    fused_attn<<<NM, 256, ATTN_SMEM>>>(cath, tilh, vtp, span, ctx);
    // 6) layernorm -> cat right half
    ln_kernel<<<NQ, 256>>>(ctx, ln_g, ln_b, cath + DD, 2 * DD);
    // 7) h1 = tanh(cat @ W_a1 + b_a1)
    gemmfp16<1, 1><<<dim3(12, 30, 1), 256, GEMM_SMEM>>>(
        cath, wa1p, b_a1, h1h, NQ, 1536, 1536, 1536, 1536, 1536, 0, 0, 0);
    // 8) f2 = h1 @ W_a2 + b_a2
    gemmfp16<0, 0><<<dim3(6, 30, 1), 256, GEMM_SMEM>>>(
        h1h, wa2p, b_a2, f2, NQ, 768, 1536, 1536, 768, 768, 0, 0, 0);
    // 9) pool
    pool_kernel<<<NM, 256>>>(f2, W_un, b_un, starts, ends, poolh);
    // 10) dense
    gemmfp16<1, 0><<<dim3(6, 1, 1), 256, GEMM_SMEM>>>(
        poolh, wdp, b_dense, tb, NM, 768, 768, 768, 768, 768, 0, 0, 0);
    // 11) classifier
    cls_kernel<<<NM, 128>>>(tb, W_cls, b_cls, out);
}

// round 14
// speedup vs baseline: 7.8806x; 1.1382x over previous
#include <cuda_runtime.h>
#include <cuda_fp16.h>
#include <math.h>
#include <stdint.h>

// Problem constants
#define NB 16
#define LSEQ 128
#define DD 768
#define HH 8
#define JR 30
#define RR 49
#define NM 128       // N*M spans
#define NQ 3840      // NM*JR rows
#define SR 784       // NB*RR rows

// ---------------- scratch ----------------
__device__ __align__(16) half  g_enc_h [16 * 49 * 2048];
__device__ __align__(16) half  g_res_h [SR * DD];
__device__ __align__(16) half  g_kv_h  [SR * 2 * HH * DD];    // kproj|vproj [784,12288]
__device__ __align__(16) half  g_til_h [16 * SR * DD];        // ktil heads 0..7 | vtil heads 8..15
__device__ __align__(16) half  g_cat_h [NQ * 2 * DD];
__device__ __align__(16) half  g_h1_h  [NQ * 2 * DD];
__device__ __align__(16) half  g_pool_h[NM * DD];
__device__ __align__(16) uint32_t g_vtilP[16 * 224 * DD];     // [ns][kpair 224][d] packed pairs
// fp32 buffers
__device__ __align__(16) float g_span [NQ * DD];
__device__ __align__(16) float g_ctx  [NQ * DD];              // also res split-K partials
__device__ __align__(16) float g_f2   [NQ * DD];
__device__ __align__(16) float g_t    [NM * DD];
// plain fp16 weights (B operands, [K][N] row-major)
__device__ __align__(16) half g_Walh [2048 * 768];
__device__ __align__(16) half g_Wkvh [768 * 12288];
__device__ __align__(16) half g_WTh  [16 * 768 * 768];        // WqT heads | Wfc blocks
__device__ __align__(16) half g_Wa1h [1536 * 1536];
__device__ __align__(16) half g_Wa2h [1536 * 768];
__device__ __align__(16) half g_Wdh  [768 * 768];

// ---------------- helpers ----------------
__device__ __forceinline__ uint32_t pack2(float a, float b) {
    __half2 h = __floats2half2_rn(a, b);
    return *(uint32_t*)&h;
}

__device__ __forceinline__ void mma16(float* c, const uint32_t* a, const uint32_t* b) {
    asm volatile(
        "mma.sync.aligned.m16n8k16.row.col.f32.f16.f16.f32 "
        "{%0,%1,%2,%3},{%4,%5,%6,%7},{%8,%9},{%0,%1,%2,%3};"
        : "+f"(c[0]), "+f"(c[1]), "+f"(c[2]), "+f"(c[3])
        : "r"(a[0]), "r"(a[1]), "r"(a[2]), "r"(a[3]), "r"(b[0]), "r"(b[1]));
}

__device__ __forceinline__ void ldsm4(uint32_t* r, uint32_t addr) {
    asm volatile("ldmatrix.sync.aligned.m8n8.x4.shared.b16 {%0,%1,%2,%3}, [%4];"
        : "=r"(r[0]), "=r"(r[1]), "=r"(r[2]), "=r"(r[3]) : "r"(addr));
}
__device__ __forceinline__ void ldsm4t(uint32_t* r, uint32_t addr) {
    asm volatile("ldmatrix.sync.aligned.m8n8.x4.trans.shared.b16 {%0,%1,%2,%3}, [%4];"
        : "=r"(r[0]), "=r"(r[1]), "=r"(r[2]), "=r"(r[3]) : "r"(addr));
}

__device__ __forceinline__ void cpa16(uint32_t saddr, const void* g) {
    asm volatile("cp.async.ca.shared.global [%0], [%1], 16;\n" :: "r"(saddr), "l"(g));
}
__device__ __forceinline__ void cpa_commit() {
    asm volatile("cp.async.commit_group;\n");
}
template<int N>
__device__ __forceinline__ void cpa_wait() {
    asm volatile("cp.async.wait_group %0;\n" :: "n"(N));
}

// ---------------- prep: generic fp32 -> fp16 convert (8 jobs) ----------------
struct CJob { const float* src; half* dst; int rows; int cols; int srcld; int dstld; };
struct CJobs { CJob j[8]; };

__global__ void convJobs(CJobs jobs) {
    CJob jb = jobs.j[blockIdx.y];
    int c4s = jb.cols >> 2;
    int total = jb.rows * c4s;
    for (int i = blockIdx.x * blockDim.x + threadIdx.x; i < total;
         i += gridDim.x * blockDim.x) {
        int r = i / c4s, c4 = i - r * c4s;
        float4 v = *(const float4*)(jb.src + (long long)r * jb.srcld + c4 * 4);
        __half2 h0 = __floats2half2_rn(v.x, v.y);
        __half2 h1 = __floats2half2_rn(v.z, v.w);
        uint2 u;
        u.x = *(uint32_t*)&h0;
        u.y = *(uint32_t*)&h1;
        *(uint2*)(jb.dst + (long long)r * jb.dstld + c4 * 4) = u;
    }
}

// Wq [768(j), 6144] -> WTh[h][d][j] = half(Wq[j][h*768+d])   (transposed head slice)
__global__ void transposeWqH(const float* __restrict__ Wq, half* __restrict__ WTh) {
    __shared__ float t[32][33];
    int h = blockIdx.z;
    int j0 = blockIdx.y * 32, d0 = blockIdx.x * 32;
    int tx = threadIdx.x, ty = threadIdx.y;   // 32 x 8
    #pragma unroll
    for (int dy = 0; dy < 32; dy += 8)
        t[ty + dy][tx] = Wq[(long long)(j0 + ty + dy) * 6144 + h * 768 + d0 + tx];
    __syncthreads();
    #pragma unroll
    for (int dy = 0; dy < 32; dy += 8)
        WTh[(long long)h * 768 * 768 + (long long)(d0 + ty + dy) * 768 + j0 + tx] =
            __float2half_rn(t[tx][ty + dy]);
}

// vtil (fp16, heads 8..15 of til) -> k-pair packed [ns][224][768] with zero pad r>=49
__global__ void vtilP_prep(const half* __restrict__ til, uint32_t* __restrict__ vp) {
    int total = 16 * 224 * DD;
    for (int i = blockIdx.x * blockDim.x + threadIdx.x; i < total;
         i += gridDim.x * blockDim.x) {
        int d = i % DD;
        int t = i / DD;
        int p = t % 224, ns = t / 224;
        int h = p / 28, rp = p - h * 28;
        int r0 = 2 * rp, r1 = 2 * rp + 1;
        const half* base = til + ((long long)(8 + h) * SR + ns * RR) * DD + d;
        half lo = (r0 < RR) ? base[(long long)r0 * DD] : __float2half(0.f);
        half hi = (r1 < RR) ? base[(long long)r1 * DD] : __float2half(0.f);
        __half2 u = __halves2half2(lo, hi);
        vp[i] = *(uint32_t*)&u;
    }
}

// res split-K combine: resh = half(p0 + p1 + bias)
__global__ void resc_kernel(const float* __restrict__ p0, const float* __restrict__ p1,
                            const float* __restrict__ bias, half* __restrict__ out) {
    int i = blockIdx.x * blockDim.x + threadIdx.x;
    if (i < SR * DD) out[i] = __float2half_rn(p0[i] + p1[i] + bias[i % DD]);
}

// ---------------- FP16 tensor-core GEMM, cp.async + ldmatrix -----------------
// BK=32 per stage (2 x k16 sub-blocks), NS=4 stages, ONE barrier/stage.
// A: half [M,K] row-major (M clamped). B: half [K,N] row-major. N%128==0, K%32==0.
// smem/stage: A 2x(128 rows x 48 B) ; B 32 rows x 272 B (16B-aligned, 4-bank
// shift per row -> conflict-free ldmatrix.trans).
#define STAGE_U32 5248
#define STAGE_BYTES (STAGE_U32 * 4)
#define GEMM_SMEM (4 * STAGE_BYTES)

template<int ACT, int OUTH>
__global__ __launch_bounds__(256, 2)
void gemmfp16(const half* __restrict__ A, const half* __restrict__ B,
              const float* __restrict__ bias, void* __restrict__ Cv,
              int M, int N, int K, int lda, int ldb, int ldc,
              long long aBS, long long bBS, long long cBS)
{
    constexpr int NS = 4;
    extern __shared__ uint32_t sm[];

    A += (long long)blockIdx.z * aBS;
    B += (long long)blockIdx.z * bBS;

    const int tid = threadIdx.x;
    const int warp = tid >> 5, lane = tid & 31;
    const int g = lane >> 2, tig = lane & 3;
    const int wm = warp & 1, wn = warp >> 1;     // 2x4 warps: 64x32 each
    const int bm = blockIdx.y * 128, bn = blockIdx.x * 128;

    // loaders
    const int la_row = tid >> 1, la_half = tid & 1;
    const half* aP = A + (long long)min(bm + la_row, M - 1) * lda + la_half * 8;
    const uint32_t a_off = la_row * 48 + la_half * 16;

    const int b_k0 = tid >> 4, b_seg = tid & 15;
    const half* bP = B + (long long)b_k0 * ldb + bn + b_seg * 8;
    const uint32_t b_off = 12288 + b_k0 * 272 + b_seg * 16;

    const uint32_t smbase = (uint32_t)__cvta_generic_to_shared(sm);

    // ldmatrix lane offsets
    const int rsel = (lane & 7) + ((lane >> 3) & 1) * 8;
    const uint32_t a_lane = rsel * 48 + (lane >> 4) * 16;
    const uint32_t b_lane = rsel * 272 + (lane >> 4) * 16;

    float acc[4][4][4];
    #pragma unroll
    for (int mt = 0; mt < 4; mt++)
        #pragma unroll
        for (int nt = 0; nt < 4; nt++)
            #pragma unroll
            for (int i = 0; i < 4; i++) acc[mt][nt][i] = 0.f;

    const int Kt = K >> 5;

    auto load_stage = [&](int buf, int kt) {
        uint32_t sb = smbase + buf * STAGE_BYTES;
        const half* ak = aP + kt * 32;
        const half* bk = bP + (long long)kt * 32 * ldb;
        cpa16(sb + a_off,        ak);
        cpa16(sb + 6144 + a_off, ak + 16);
        cpa16(sb + b_off,        bk);
        cpa16(sb + b_off + 4352, bk + (long long)16 * ldb);
    };

    load_stage(0, 0); cpa_commit();
    load_stage(1, 1); cpa_commit();
    load_stage(2, 2); cpa_commit();

    for (int kt = 0; kt < Kt; kt++) {
        cpa_wait<NS - 2>();
        __syncthreads();

        const int buf = kt & 3;
        const uint32_t sb = smbase + buf * STAGE_BYTES;

        #pragma unroll
        for (int s2 = 0; s2 < 2; s2++) {
            const uint32_t abase = sb + s2 * 6144 + wm * 64 * 48 + a_lane;
            const uint32_t bbase = sb + 12288 + s2 * 4352 + wn * 64 + b_lane;
            uint32_t af[4][4], bf[2][4];
            #pragma unroll
            for (int mt = 0; mt < 4; mt++)
                ldsm4(af[mt], abase + mt * 768);
            ldsm4t(bf[0], bbase);
            ldsm4t(bf[1], bbase + 32);
            #pragma unroll
            for (int mt = 0; mt < 4; mt++)
                #pragma unroll
                for (int nt = 0; nt < 4; nt++)
                    mma16(acc[mt][nt], af[mt], &bf[nt >> 1][(nt & 1) * 2]);
        }

        int nk = kt + NS - 1;
        if (nk < Kt) load_stage(nk & 3, nk);
        cpa_commit();
    }

    #pragma unroll
    for (int mt = 0; mt < 4; mt++) {
        int r0 = bm + wm * 64 + mt * 16 + g;
        int r1 = r0 + 8;
        #pragma unroll
        for (int nt = 0; nt < 4; nt++) {
            int c = bn + wn * 32 + nt * 8 + 2 * tig;
            float b0 = bias ? bias[c] : 0.f;
            float b1 = bias ? bias[c + 1] : 0.f;
            float v0 = acc[mt][nt][0] + b0, v1 = acc[mt][nt][1] + b1;
            float v2 = acc[mt][nt][2] + b0, v3 = acc[mt][nt][3] + b1;
            if (ACT == 1) { v0 = tanhf(v0); v1 = tanhf(v1); v2 = tanhf(v2); v3 = tanhf(v3); }
            if (OUTH) {
                half* C = (half*)Cv + (long long)blockIdx.z * cBS;
                if (r0 < M) *(uint32_t*)(C + (long long)r0 * ldc + c) = pack2(v0, v1);
                if (r1 < M) *(uint32_t*)(C + (long long)r1 * ldc + c) = pack2(v2, v3);
            } else {
                float* C = (float*)Cv + (long long)blockIdx.z * cBS;
                if (r0 < M) *(float2*)(C + (long long)r0 * ldc + c) = make_float2(v0, v1);
                if (r1 < M) *(float2*)(C + (long long)r1 * ldc + c) = make_float2(v2, v3);
            }
        }
    }
}

// ---------------- fused attention: QK^T + softmax + AV + residual ------------
// One CTA per span s. 8 warps; warp h owns head h in QK phase.
#define SP_OFF  0                    // span fp16: [32][388] u32 (rows 0..29 valid)
#define KT_OFF  12416                // QK: [8][56][36] u32 ; AV: [224][72] u32
#define P16_OFF 28544                // P fp16: [32][228] u32 (k = h*56+r)
#define LG_OFF  35840                // logits fp32: [8][32][58]
#define ATTN_SMEM ((35840 + 14848) * 4)   // 202752 B

__global__ __launch_bounds__(256, 1)
void fused_attn(const half* __restrict__ cat, const half* __restrict__ til,
                const uint32_t* __restrict__ vtilP, const float* __restrict__ span,
                float* __restrict__ ctx)
{
    extern __shared__ uint32_t sm[];
    const int s = blockIdx.x;
    const int ns = s >> 3;
    const int tid = threadIdx.x, warp = tid >> 5, lane = tid & 31;
    const int g = lane >> 2, tig = lane & 3;
    const uint32_t smb = (uint32_t)__cvta_generic_to_shared(sm);

    // preload span tile (30 rows x 768 halves = 96 cpa16 per row)
    for (int i = tid; i < 30 * 96; i += 256) {
        int q = i / 96, j = i - q * 96;
        cpa16(smb + (SP_OFF + q * 388) * 4 + j * 16,
              cat + (long long)(s * JR + q) * 1536 + j * 8);
    }

    // ---- Phase A: logits ----
    float acc[2][7][4];
    #pragma unroll
    for (int mt = 0; mt < 2; mt++)
        #pragma unroll
        for (int nt = 0; nt < 7; nt++)
            #pragma unroll
            for (int i = 0; i < 4; i++) acc[mt][nt][i] = 0.f;

    const int h = warp;
    for (int kc = 0; kc < 12; kc++) {
        for (int i = tid; i < 8 * RR * 8; i += 256) {
            int hh = i / (RR * 8), rem = i - hh * (RR * 8);
            int r = rem >> 3, j = rem & 7;
            cpa16(smb + (KT_OFF + (hh * 56 + r) * 36) * 4 + j * 16,
                  til + ((long long)hh * SR + ns * RR + r) * DD + kc * 64 + j * 8);
        }
        cpa_commit();
        cpa_wait<0>();
        __syncthreads();

        const uint32_t* sp = sm + SP_OFF;
        const uint32_t* kt = sm + KT_OFF + h * 56 * 36;
        #pragma unroll
        for (int k4 = 0; k4 < 4; k4++) {
            uint32_t af[2][4], bf[7][2];
            #pragma unroll
            for (int mt = 0; mt < 2; mt++) {
                const uint32_t* p = sp + (mt * 16 + g) * 388 + kc * 32 + k4 * 8;
                af[mt][0] = p[tig];
                af[mt][1] = p[8 * 388 + tig];
                af[mt][2] = p[tig + 4];
                af[mt][3] = p[8 * 388 + tig + 4];
            }
            #pragma unroll
            for (int nt = 0; nt < 7; nt++) {
                bf[nt][0] = kt[(nt * 8 + g) * 36 + k4 * 8 + tig];
                bf[nt][1] = kt[(nt * 8 + g) * 36 + k4 * 8 + tig + 4];
            }
            #pragma unroll
            for (int mt = 0; mt < 2; mt++)
                #pragma unroll
                for (int nt = 0; nt < 7; nt++)
                    mma16(acc[mt][nt], af[mt], bf[nt]);
        }
        __syncthreads();
    }

    // store scaled logits to smem
    {
        float* lg = (float*)(sm + LG_OFF) + h * 32 * 58;
        const float scale = rsqrtf((float)DD);
        #pragma unroll
        for (int mt = 0; mt < 2; mt++) {
            int r0 = mt * 16 + g, r1 = r0 + 8;
            #pragma unroll
            for (int nt = 0; nt < 7; nt++) {
                int c = nt * 8 + 2 * tig;
                lg[r0 * 58 + c]     = acc[mt][nt][0] * scale;
                lg[r0 * 58 + c + 1] = acc[mt][nt][1] * scale;
                lg[r1 * 58 + c]     = acc[mt][nt][2] * scale;
                lg[r1 * 58 + c + 1] = acc[mt][nt][3] * scale;
            }
        }
    }
    __syncwarp();

    // ---- softmax (warp h handles its own head) ----
    {
        const float* lg = (const float*)(sm + LG_OFF) + h * 32 * 58;
        uint32_t* P = sm + P16_OFF;
        int rp = lane;
        for (int q = 0; q < JR; q++) {
            float v0 = -3.0e38f, v1 = -3.0e38f;
            if (rp < 25) {
                int r0 = 2 * rp, r1 = 2 * rp + 1;
                if (r0 < RR) v0 = lg[q * 58 + r0];
                if (r1 < RR) v1 = lg[q * 58 + r1];
            }
            float m = fmaxf(v0, v1);
            #pragma unroll
            for (int o = 16; o; o >>= 1) m = fmaxf(m, __shfl_xor_sync(0xffffffffu, m, o));
            float e0 = (v0 > -1.0e38f) ? expf(v0 - m) : 0.f;
            float e1 = (v1 > -1.0e38f) ? expf(v1 - m) : 0.f;
            float sum = e0 + e1;
            #pragma unroll
            for (int o = 16; o; o >>= 1) sum += __shfl_xor_sync(0xffffffffu, sum, o);
            float inv = 1.f / sum;
            if (rp < 28)
                P[q * 228 + h * 28 + rp] = pack2(e0 * inv, e1 * inv);
        }
    }
    __syncthreads();

    // ---- Phase B: ctx = P @ V + span ----
    for (int dn = 0; dn < 12; dn++) {
        for (int i = tid; i < 224 * 16; i += 256) {
            int p = i >> 4, j = i & 15;
            cpa16(smb + (KT_OFF + p * 72) * 4 + j * 16,
                  vtilP + ((long long)ns * 224 + p) * DD + dn * 64 + j * 4);
        }
        cpa_commit();
        cpa_wait<0>();
        __syncthreads();

        float bacc[2][4];
        #pragma unroll
        for (int mt = 0; mt < 2; mt++)
            #pragma unroll
            for (int i = 0; i < 4; i++) bacc[mt][i] = 0.f;

        const uint32_t* Pp = sm + P16_OFF;
        const uint32_t* vp = sm + KT_OFF;
        #pragma unroll
        for (int k28 = 0; k28 < 28; k28++) {
            uint32_t af[2][4], bf[2];
            #pragma unroll
            for (int mt = 0; mt < 2; mt++) {
                const uint32_t* p = Pp + (mt * 16 + g) * 228 + k28 * 8;
                af[mt][0] = p[tig];
                af[mt][1] = p[8 * 228 + tig];
                af[mt][2] = p[tig + 4];
                af[mt][3] = p[8 * 228 + tig + 4];
            }
            bf[0] = vp[(k28 * 8 + tig) * 72 + warp * 8 + g];
            bf[1] = vp[(k28 * 8 + tig + 4) * 72 + warp * 8 + g];
            mma16(bacc[0], af[0], bf);
            mma16(bacc[1], af[1], bf);
        }

        #pragma unroll
        for (int mt = 0; mt < 2; mt++) {
            int r0 = mt * 16 + g, r1 = r0 + 8;
            int c = dn * 64 + warp * 8 + 2 * tig;
            if (r0 < JR) {
                const float2 sp2 = *(const float2*)(span + (long long)(s * JR + r0) * DD + c);
                *(float2*)(ctx + (long long)(s * JR + r0) * DD + c) =
                    make_float2(bacc[mt][0] + sp2.x, bacc[mt][1] + sp2.y);
            }
            if (r1 < JR) {
                const float2 sp2 = *(const float2*)(span + (long long)(s * JR + r1) * DD + c);
                *(float2*)(ctx + (long long)(s * JR + r1) * DD + c) =
                    make_float2(bacc[mt][2] + sp2.x, bacc[mt][3] + sp2.y);
            }
        }
        __syncthreads();
    }
}

// ---------------- span gather (fp32 -> span, fp16 -> cat left) -------------
__global__ void gather_kernel(const float* __restrict__ seq,
                              const int* __restrict__ starts,
                              float* __restrict__ out, half* __restrict__ cat)
{
    int sq = blockIdx.x;
    int s = sq / JR, q = sq - s * JR;
    int gstart = starts[s] + (s >> 3) * LSEQ;
    int idx = min(gstart + q, NB * LSEQ - 1);
    const float4* src = (const float4*)(seq + (long long)idx * DD);
    float4* dst = (float4*)(out + (long long)sq * DD);
    uint2* dst2 = (uint2*)(cat + (long long)sq * 2 * DD);
    for (int i = threadIdx.x; i < DD / 4; i += blockDim.x) {
        float4 v = src[i];
        dst[i] = v;
        uint2 u;
        u.x = pack2(v.x, v.y);
        u.y = pack2(v.z, v.w);
        dst2[i] = u;
    }
}

// ---------------- layernorm (fp16 strided output into cat right) -----------
__global__ __launch_bounds__(256)
void ln_kernel(const float* __restrict__ X, const float* __restrict__ g,
               const float* __restrict__ b, half* __restrict__ Y, int ostride)
{
    int r = blockIdx.x;
    int t = threadIdx.x;
    const float* x = X + (long long)r * DD;
    float v0 = x[t], v1 = x[t + 256], v2 = x[t + 512];
    __shared__ float red[8];

    float s = v0 + v1 + v2;
    #pragma unroll
    for (int o = 16; o; o >>= 1) s += __shfl_xor_sync(0xffffffffu, s, o);
    if ((t & 31) == 0) red[t >> 5] = s;
    __syncthreads();
    if (t == 0) { float z = 0.f; for (int i = 0; i < 8; i++) z += red[i]; red[0] = z; }
    __syncthreads();
    float mu = red[0] * (1.0f / DD);
    __syncthreads();

    float d0 = v0 - mu, d1 = v1 - mu, d2 = v2 - mu;
    float ss = d0 * d0 + d1 * d1 + d2 * d2;
    #pragma unroll
    for (int o = 16; o; o >>= 1) ss += __shfl_xor_sync(0xffffffffu, ss, o);
    if ((t & 31) == 0) red[t >> 5] = ss;
    __syncthreads();
    if (t == 0) { float z = 0.f; for (int i = 0; i < 8; i++) z += red[i]; red[0] = z; }
    __syncthreads();
    float inv = rsqrtf(red[0] * (1.0f / DD) + 1e-5f);

    half* y = Y + (long long)r * ostride;
    y[t]       = __float2half_rn(d0 * inv * g[t]       + b[t]);
    y[t + 256] = __float2half_rn(d1 * inv * g[t + 256] + b[t + 256]);
    y[t + 512] = __float2half_rn(d2 * inv * g[t + 512] + b[t + 512]);
}

// ---------------- unary score + masked softmax + pooling --------------------
__global__ __launch_bounds__(256)
void pool_kernel(const float* __restrict__ F2, const float* __restrict__ W_un,
                 const float* __restrict__ b_un, const int* __restrict__ starts,
                 const int* __restrict__ ends, half* __restrict__ pooled)
{
    int s = blockIdx.x;
    __shared__ float sc[JR];
    __shared__ float pr[32];
    int tid = threadIdx.x, warp = tid >> 5, lane = tid & 31;

    for (int q = warp; q < JR; q += 8) {
        const float* row = F2 + (long long)(s * JR + q) * DD;
        float acc = 0.f;
        for (int k = lane; k < DD; k += 32) acc += row[k] * W_un[k];
        #pragma unroll
        for (int o = 16; o; o >>= 1) acc += __shfl_xor_sync(0xffffffffu, acc, o);
        if (lane == 0) sc[q] = acc + b_un[0];
    }
    __syncthreads();

    if (tid < 32) {
        int width = ends[s] - starts[s] + 1;
        float v = -3.0e38f;
        if (tid < JR) {
            v = sc[tid];
            if (tid >= width) v += -10000.0f;
        }
        float m = v;
        #pragma unroll
        for (int o = 16; o; o >>= 1) m = fmaxf(m, __shfl_xor_sync(0xffffffffu, m, o));
        float e = (tid < JR) ? expf(v - m) : 0.f;
        float sum = e;
        #pragma unroll
        for (int o = 16; o; o >>= 1) sum += __shfl_xor_sync(0xffffffffu, sum, o);
        pr[tid] = (tid < JR) ? e / sum : 0.f;
    }
    __syncthreads();

    for (int o = tid; o < DD; o += 256) {
        float acc = 0.f;
        #pragma unroll
        for (int q = 0; q < JR; q++)
            acc += pr[q] * F2[(long long)(s * JR + q) * DD + o];
        pooled[(long long)s * DD + o] = __float2half_rn(acc);
    }
}

// ---------------- classifier ------------------------------------------------
__global__ void cls_kernel(const float* __restrict__ T, const float* __restrict__ Wc,
                           const float* __restrict__ bc, float* __restrict__ out)
{
    int s = blockIdx.x;
    int c = threadIdx.x >> 5, lane = threadIdx.x & 31;
    const float* t = T + (long long)s * DD;
    float acc = 0.f;
    for (int k = lane; k < DD; k += 32) acc += t[k] * Wc[k * 4 + c];
    #pragma unroll
    for (int o = 16; o; o >>= 1) acc += __shfl_xor_sync(0xffffffffu, acc, o);
    if (lane == 0) out[s * 4 + c] = acc + bc[c];
}

// ---------------- launcher --------------------------------------------------
extern "C" void kernel_launch(void* const* d_in, const int* in_sizes, int n_in,
                              void* d_out, int out_size)
{
    const float* enc_img  = (const float*)d_in[0];
    const float* seq      = (const float*)d_in[1];
    const int*   starts   = (const int*)d_in[3];
    const int*   ends     = (const int*)d_in[4];
    const float* W_align  = (const float*)d_in[5];
    const float* b_align  = (const float*)d_in[6];
    const float* Wq       = (const float*)d_in[7];
    const float* Wk       = (const float*)d_in[8];
    const float* Wv       = (const float*)d_in[9];
    const float* Wfc      = (const float*)d_in[10];
    const float* ln_g     = (const float*)d_in[11];
    const float* ln_b     = (const float*)d_in[12];
    const float* W_a1     = (const float*)d_in[13];
    const float* b_a1     = (const float*)d_in[14];
    const float* W_a2     = (const float*)d_in[15];
    const float* b_a2     = (const float*)d_in[16];
    const float* W_un     = (const float*)d_in[17];
    const float* b_un     = (const float*)d_in[18];
    const float* W_dense  = (const float*)d_in[19];
    const float* b_dense  = (const float*)d_in[20];
    const float* W_cls    = (const float*)d_in[21];
    const float* b_cls    = (const float*)d_in[22];
    float* out = (float*)d_out;

    half *ench, *resh, *kvh, *tilh, *cath, *h1h, *poolh;
    half *walh, *wkvh, *wth, *wa1h, *wa2h, *wdh;
    float *span, *ctx, *f2, *tb;
    uint32_t *vtp;
    cudaGetSymbolAddress((void**)&ench,  g_enc_h);
    cudaGetSymbolAddress((void**)&resh,  g_res_h);
    cudaGetSymbolAddress((void**)&kvh,   g_kv_h);
    cudaGetSymbolAddress((void**)&tilh,  g_til_h);
    cudaGetSymbolAddress((void**)&cath,  g_cat_h);
    cudaGetSymbolAddress((void**)&h1h,   g_h1_h);
    cudaGetSymbolAddress((void**)&poolh, g_pool_h);
    cudaGetSymbolAddress((void**)&span,  g_span);
    cudaGetSymbolAddress((void**)&ctx,   g_ctx);
    cudaGetSymbolAddress((void**)&f2,    g_f2);
    cudaGetSymbolAddress((void**)&tb,    g_t);
    cudaGetSymbolAddress((void**)&walh,  g_Walh);
    cudaGetSymbolAddress((void**)&wkvh,  g_Wkvh);
    cudaGetSymbolAddress((void**)&wth,   g_WTh);
    cudaGetSymbolAddress((void**)&wa1h,  g_Wa1h);
    cudaGetSymbolAddress((void**)&wa2h,  g_Wa2h);
    cudaGetSymbolAddress((void**)&wdh,   g_Wdh);
    cudaGetSymbolAddress((void**)&vtp,   g_vtilP);

    cudaFuncSetAttribute(gemmfp16<0, 0>, cudaFuncAttributeMaxDynamicSharedMemorySize, GEMM_SMEM);
    cudaFuncSetAttribute(gemmfp16<0, 1>, cudaFuncAttributeMaxDynamicSharedMemorySize, GEMM_SMEM);
    cudaFuncSetAttribute(gemmfp16<1, 0>, cudaFuncAttributeMaxDynamicSharedMemorySize, GEMM_SMEM);
    cudaFuncSetAttribute(gemmfp16<1, 1>, cudaFuncAttributeMaxDynamicSharedMemorySize, GEMM_SMEM);
    cudaFuncSetAttribute(fused_attn, cudaFuncAttributeMaxDynamicSharedMemorySize, ATTN_SMEM);

    // prep: fp32 -> fp16 conversions (8 plain jobs) + Wq head transpose
    CJobs cj;
    cj.j[0] = { enc_img, ench, 16 * 49, 2048, 2048, 2048 };
    cj.j[1] = { W_align, walh, 2048, 768, 768, 768 };
    cj.j[2] = { Wk, wkvh, 768, 6144, 6144, 12288 };
    cj.j[3] = { Wv, wkvh + 6144, 768, 6144, 6144, 12288 };
    cj.j[4] = { Wfc, wth + 8LL * 768 * 768, 6144, 768, 768, 768 };
    cj.j[5] = { W_a1, wa1h, 1536, 1536, 1536, 1536 };
    cj.j[6] = { W_a2, wa2h, 1536, 768, 768, 768 };       // FIX: srcld = 768
    cj.j[7] = { W_dense, wdh, 768, 768, 768, 768 };
    convJobs<<<dim3(256, 8), 256>>>(cj);
    transposeWqH<<<dim3(24, 24, 8), dim3(32, 8)>>>(Wq, wth);

    // 0) res split-K=2: partials into ctx scratch, then combine
    //    FIX: bBS in halves = 1024 k-rows * 768 cols
    gemmfp16<0, 0><<<dim3(6, 7, 2), 256, GEMM_SMEM>>>(
        ench, walh, nullptr, ctx, SR, 768, 1024, 2048, 768, 768,
        1024LL, 1024LL * 768LL, (long long)SR * 768);
    resc_kernel<<<(SR * DD + 255) / 256, 256>>>(ctx, ctx + (long long)SR * DD, b_align, resh);

    // 1) kvproj = res @ [Wk|Wv]     [784,12288] half out
    gemmfp16<0, 1><<<dim3(96, 7, 1), 256, GEMM_SMEM>>>(
        resh, wkvh, nullptr, kvh, SR, 12288, 768, 768, 12288, 12288, 0, 0, 0);
    // 2) til (fp16): z<8 ktil_h = kproj_h @ WqT_h; z>=8 vtil_h = vproj_h @ Wfc_h
    gemmfp16<0, 1><<<dim3(6, 7, 16), 256, GEMM_SMEM>>>(
        kvh, wth, nullptr, tilh, SR, 768, 768, 12288, 768, 768,
        768LL, 768LL * 768LL, (long long)SR * 768);
    // 3) span gather
    gather_kernel<<<NQ, 192>>>(seq, starts, span, cath);
    // 4) vtil pack for AV
    vtilP_prep<<<2048, 256>>>(tilh, vtp);
    // 5) fused attention -> ctx
    fused_attn<<<NM, 256, ATTN_SMEM>>>(cath, tilh, vtp, span, ctx);
    // 6) layernorm -> cat right half
    ln_kernel<<<NQ, 256>>>(ctx, ln_g, ln_b, cath + DD, 2 * DD);
    // 7) h1 = tanh(cat @ W_a1 + b_a1)
    gemmfp16<1, 1><<<dim3(12, 30, 1), 256, GEMM_SMEM>>>(
        cath, wa1h, b_a1, h1h, NQ, 1536, 1536, 1536, 1536, 1536, 0, 0, 0);
    // 8) f2 = h1 @ W_a2 + b_a2
    gemmfp16<0, 0><<<dim3(6, 30, 1), 256, GEMM_SMEM>>>(
        h1h, wa2h, b_a2, f2, NQ, 768, 1536, 1536, 768, 768, 0, 0, 0);
    // 9) pool
    pool_kernel<<<NM, 256>>>(f2, W_un, b_un, starts, ends, poolh);
    // 10) dense
    gemmfp16<1, 0><<<dim3(6, 1, 1), 256, GEMM_SMEM>>>(
        poolh, wdh, b_dense, tb, NM, 768, 768, 768, 768, 768, 0, 0, 0);
    // 11) classifier
    cls_kernel<<<NM, 128>>>(tb, W_cls, b_cls, out);
}